// round 13
// baseline (speedup 1.0000x reference)
#include <cuda_runtime.h>
#include <cuda_bf16.h>
#include <cuda_fp16.h>

#define BATCH 4096
#define DIM   1024
#define NS    64
#define LBLK  11
#define NCODE 2048

typedef unsigned long long u64;

// ---- device-global scratch (static; no runtime alloc) ----
__device__ float  g_E0[NS], g_E1[NS], g_Pi[NS];
__device__ float  g_L1[2 * NS * NS];                  // normal [k][o]
__device__ float  g_L2[4 * NS * NS],  g_L2t[4 * NS * NS];
__device__ float  g_L3[8 * NS * NS];                  // L3[v] = L2[v>>1] @ L1[v&1]
__device__ float  g_L4[16 * NS * NS], g_L4t[16 * NS * NS];
__device__ float  g_L8t[256 * NS * NS];               // only transposed needed
__device__ int    g_e1[2], g_e2[4], g_e3[8], g_e4[16], g_e8[256], g_e11[NCODE];
// fp8 e4m3 table, permuted: byte(c,o,k) = c*4096 + ((o<32?0:4)+(k>>4))*512 + (o&31)*16 + (k&15)
__device__ uint4  g_Pt4[NCODE * 256];    // 8 MB
__device__ double g_acc;
__device__ unsigned g_done;

// ---- packed helpers ----
__device__ __forceinline__ u64 pk2(float lo, float hi) {
    u64 r; asm("mov.b64 %0, {%1,%2};" : "=l"(r) : "f"(lo), "f"(hi)); return r;
}
__device__ __forceinline__ void upk2(u64 v, float &lo, float &hi) {
    asm("mov.b64 {%0,%1}, %2;" : "=f"(lo), "=f"(hi) : "l"(v));
}
__device__ __forceinline__ u64 fma2(u64 a, u64 b, u64 c) {
    u64 d; asm("fma.rn.f32x2 %0, %1, %2, %3;" : "=l"(d) : "l"(a), "l"(b), "l"(c)); return d;
}
__device__ __forceinline__ unsigned short f2_e4m3x2(float hi, float lo) {
    unsigned short r;
    asm("cvt.rn.satfinite.e4m3x2.f32 %0, %1, %2;" : "=h"(r) : "f"(hi), "f"(lo));
    return r;
}
__device__ __forceinline__ __half2 e4m3x2_h2(unsigned short s) {
    unsigned r;
    asm("cvt.rn.f16x2.e4m3x2 %0, %1;" : "=r"(r) : "h"(s));
    return *(__half2*)&r;
}
__device__ __forceinline__ __half2 as_h2(unsigned w) { return *(__half2*)&w; }

// ---- classic 4x4 GEMM (prep L2 stage only; A transposed, not duplicated) ----
__device__ __forceinline__ void gemm4x4(const float* __restrict__ At, int strideF,
                                        const float* __restrict__ B,
                                        int jc, int rc, float out[4][4]) {
    u64 acc[4][2];
#pragma unroll
    for (int r = 0; r < 4; r++) { acc[r][0] = 0ull; acc[r][1] = 0ull; }
#pragma unroll 16
    for (int k = 0; k < NS; k++) {
        const float4 av = *(const float4*)(At + k * strideF + 4 * rc);
        const float4 bv = *(const float4*)(B  + k * NS      + 4 * jc);
        const u64 c01 = ((const u64*)&bv)[0];
        const u64 c23 = ((const u64*)&bv)[1];
        const u64 a0 = pk2(av.x, av.x), a1 = pk2(av.y, av.y);
        const u64 a2 = pk2(av.z, av.z), a3 = pk2(av.w, av.w);
        acc[0][0] = fma2(c01, a0, acc[0][0]); acc[0][1] = fma2(c23, a0, acc[0][1]);
        acc[1][0] = fma2(c01, a1, acc[1][0]); acc[1][1] = fma2(c23, a1, acc[1][1]);
        acc[2][0] = fma2(c01, a2, acc[2][0]); acc[2][1] = fma2(c23, a2, acc[2][1]);
        acc[3][0] = fma2(c01, a3, acc[3][0]); acc[3][1] = fma2(c23, a3, acc[3][1]);
    }
#pragma unroll
    for (int r = 0; r < 4; r++) {
        upk2(acc[r][0], out[r][0], out[r][1]);
        upk2(acc[r][1], out[r][2], out[r][3]);
    }
}

// ---- duplicated-A 4x8 GEMM (128 threads: jc = tid&7, rc = tid>>3) ----
// Atd[k*128 + 2r] = Atd[k*128 + 2r+1] = A[r][k]
// out[r][c] = sum_k A[4rc+r][k] * B[k][8jc+c] ; k accumulated sequentially
__device__ __forceinline__ void gemm4x8_dup(const float* __restrict__ Atd,
                                            const float* __restrict__ B,
                                            int jc, int rc, float out[4][8]) {
    u64 acc[4][4];
#pragma unroll
    for (int r = 0; r < 4; r++)
#pragma unroll
        for (int q = 0; q < 4; q++) acc[r][q] = 0ull;
#pragma unroll 16
    for (int k = 0; k < NS; k++) {
        const ulonglong2 a01 = *(const ulonglong2*)(Atd + k * 128 + 8 * rc);
        const ulonglong2 a23 = *(const ulonglong2*)(Atd + k * 128 + 8 * rc + 4);
        const float4 b0 = *(const float4*)(B + k * NS + 8 * jc);
        const float4 b1 = *(const float4*)(B + k * NS + 8 * jc + 4);
        const u64 c01 = ((const u64*)&b0)[0];
        const u64 c23 = ((const u64*)&b0)[1];
        const u64 c45 = ((const u64*)&b1)[0];
        const u64 c67 = ((const u64*)&b1)[1];
        acc[0][0] = fma2(c01, a01.x, acc[0][0]); acc[0][1] = fma2(c23, a01.x, acc[0][1]);
        acc[0][2] = fma2(c45, a01.x, acc[0][2]); acc[0][3] = fma2(c67, a01.x, acc[0][3]);
        acc[1][0] = fma2(c01, a01.y, acc[1][0]); acc[1][1] = fma2(c23, a01.y, acc[1][1]);
        acc[1][2] = fma2(c45, a01.y, acc[1][2]); acc[1][3] = fma2(c67, a01.y, acc[1][3]);
        acc[2][0] = fma2(c01, a23.x, acc[2][0]); acc[2][1] = fma2(c23, a23.x, acc[2][1]);
        acc[2][2] = fma2(c45, a23.x, acc[2][2]); acc[2][3] = fma2(c67, a23.x, acc[2][3]);
        acc[3][0] = fma2(c01, a23.y, acc[3][0]); acc[3][1] = fma2(c23, a23.y, acc[3][1]);
        acc[3][2] = fma2(c45, a23.y, acc[3][2]); acc[3][3] = fma2(c67, a23.y, acc[3][3]);
    }
#pragma unroll
    for (int r = 0; r < 4; r++)
#pragma unroll
        for (int q = 0; q < 4; q++)
            upk2(acc[r][q], out[r][2 * q], out[r][2 * q + 1]);
}

// stage transposed global [k*64+r] -> duplicated smem [k*128 + 2r{,+1}], 128 thr
__device__ __forceinline__ void stage_dup128(const float* __restrict__ src_t,
                                             float* __restrict__ dst) {
    const int tid = threadIdx.x;
#pragma unroll
    for (int i = 0; i < 8; i++) {
        const int f  = tid + 128 * i;       // float4 index
        const float4 v = ((const float4*)src_t)[f];
        const int k  = f >> 4, r4 = (f & 15) * 4;
        float4* d = (float4*)(dst + k * 128 + 2 * r4);
        d[0] = make_float4(v.x, v.x, v.y, v.y);
        d[1] = make_float4(v.z, v.z, v.w, v.w);
    }
}
__device__ __forceinline__ void stage_nrm128(const float* __restrict__ src,
                                             float* __restrict__ dst) {
    const int tid = threadIdx.x;
#pragma unroll
    for (int i = 0; i < 8; i++)
        ((float4*)dst)[tid + 128 * i] = ((const float4*)src)[tid + 128 * i];
}

// block-wide max over per-thread mx (128 thr), result broadcast via smem
__device__ __forceinline__ float blockmax128(float mx, float* sred4, int lane, int w) {
#pragma unroll
    for (int off = 16; off > 0; off >>= 1)
        mx = fmaxf(mx, __shfl_xor_sync(0xffffffffu, mx, off));
    if (lane == 0) sred4[w] = mx;
    __syncthreads();
    return fmaxf(fmaxf(sred4[0], sred4[1]), fmaxf(sred4[2], sred4[3]));
}

// ============================================================================
// prep: softmaxes + L1 + L2 in ONE kernel (unchanged)
// ============================================================================
__global__ void __launch_bounds__(1024)
prep_kernel(const float* __restrict__ Tr,
            const float* __restrict__ Em,
            const float* __restrict__ Pi) {
    extern __shared__ float dynP[];
    float* sL1n = dynP;
    float* sL1t = dynP + 8192;

    __shared__ float rowm[NS], rowinv[NS];
    __shared__ float sE[2][NS];
    __shared__ float sred[32];
    __shared__ float sbcA[4];
    __shared__ int   seiA[4];

    const int tid  = threadIdx.x;
    const int lane = tid & 31;
    const int w    = tid >> 5;

    if (tid == 0) { g_acc = 0.0; g_done = 0u; }

#pragma unroll
    for (int rr = 0; rr < 2; rr++) {
        const int r = w + rr * 32;
        const float v0 = Tr[r * NS + lane];
        const float v1 = Tr[r * NS + lane + 32];
        float m = fmaxf(v0, v1);
#pragma unroll
        for (int off = 16; off > 0; off >>= 1)
            m = fmaxf(m, __shfl_xor_sync(0xffffffffu, m, off));
        const float e0 = expf(v0 - m), e1v = expf(v1 - m);
        float s = e0 + e1v;
#pragma unroll
        for (int off = 16; off > 0; off >>= 1)
            s += __shfl_xor_sync(0xffffffffu, s, off);
        if (lane == 0) { rowm[r] = m; rowinv[r] = 1.f / s; }
    }
    if (tid < NS) {
        const float a = Em[tid * 2 + 0], b2 = Em[tid * 2 + 1];
        const float mm = fmaxf(a, b2);
        const float ea = expf(a - mm), eb = expf(b2 - mm);
        const float is = 1.f / (ea + eb);
        sE[0][tid] = ea * is;  sE[1][tid] = eb * is;
        g_E0[tid] = ea * is;   g_E1[tid] = eb * is;
    }
    if (w == 1) {
        const float v0 = Pi[lane], v1 = Pi[lane + 32];
        float m = fmaxf(v0, v1);
#pragma unroll
        for (int off = 16; off > 0; off >>= 1)
            m = fmaxf(m, __shfl_xor_sync(0xffffffffu, m, off));
        const float e0 = expf(v0 - m), e1v = expf(v1 - m);
        float s = e0 + e1v;
#pragma unroll
        for (int off = 16; off > 0; off >>= 1)
            s += __shfl_xor_sync(0xffffffffu, s, off);
        const float inv = 1.f / s;
        g_Pi[lane] = e0 * inv;  g_Pi[lane + 32] = e1v * inv;
    }
    __syncthreads();

    for (int y = 0; y < 2; y++) {
        float vv[4], vmax = 0.f;
#pragma unroll
        for (int i = 0; i < 4; i++) {
            const int idx = tid + i * 1024;
            const int k = idx >> 6, o = idx & 63;
            const float v = expf(Tr[idx] - rowm[k]) * rowinv[k] * sE[y][o];
            vv[i] = v; vmax = fmaxf(vmax, v);
        }
#pragma unroll
        for (int off = 16; off > 0; off >>= 1)
            vmax = fmaxf(vmax, __shfl_xor_sync(0xffffffffu, vmax, off));
        if (lane == 0) sred[w] = vmax;
        __syncthreads();
        if (tid < 32) {
            float m = sred[lane];
#pragma unroll
            for (int off = 16; off > 0; off >>= 1)
                m = fmaxf(m, __shfl_xor_sync(0xffffffffu, m, off));
            if (lane == 0) {
                const int e = (__float_as_int(m) >> 23) - 127;
                seiA[y] = e;  g_e1[y] = e;
                sbcA[y] = __int_as_float((127 - e) << 23);
            }
        }
        __syncthreads();
        const float sc = sbcA[y];
#pragma unroll
        for (int i = 0; i < 4; i++) {
            const int idx = tid + i * 1024;
            const int k = idx >> 6, o = idx & 63;
            const float v = vv[i] * sc;
            sL1n[y * 4096 + idx]         = v;
            sL1t[y * 4352 + o * 68 + k]  = v;
            g_L1[y * 4096 + idx]         = v;
        }
        __syncthreads();
    }

    {
        const int g    = tid >> 8;
        const int gtid = tid & 255;
        const int jc   = gtid & 15;
        const int rc   = gtid >> 4;
        float out[4][4];
        gemm4x4(sL1t + (g >> 1) * 4352, 68, sL1n + (g & 1) * 4096, jc, rc, out);
        float mx = 0.f;
#pragma unroll
        for (int r = 0; r < 4; r++)
#pragma unroll
            for (int c = 0; c < 4; c++) mx = fmaxf(mx, out[r][c]);
#pragma unroll
        for (int off = 16; off > 0; off >>= 1)
            mx = fmaxf(mx, __shfl_xor_sync(0xffffffffu, mx, off));
        if (lane == 0) sred[w] = mx;
        __syncthreads();
        if (tid < 4) {
            float m = sred[8 * tid];
#pragma unroll
            for (int q = 1; q < 8; q++) m = fmaxf(m, sred[8 * tid + q]);
            const int e = (__float_as_int(m) >> 23) - 127;
            sbcA[tid] = __int_as_float((127 - e) << 23);
            g_e2[tid] = seiA[tid >> 1] + seiA[tid & 1] + e;
        }
        __syncthreads();
        const float sc = sbcA[g];
#pragma unroll
        for (int r = 0; r < 4; r++) {
            float4 wv = make_float4(out[r][0] * sc, out[r][1] * sc,
                                    out[r][2] * sc, out[r][3] * sc);
            *(float4*)(g_L2 + g * 4096 + (4 * rc + r) * NS + 4 * jc) = wv;
        }
#pragma unroll
        for (int c = 0; c < 4; c++) {
            float4 wv = make_float4(out[0][c] * sc, out[1][c] * sc,
                                    out[2][c] * sc, out[3][c] * sc);
            *(float4*)(g_L2t + g * 4096 + (4 * jc + c) * NS + 4 * rc) = wv;
        }
    }
}

// ============================================================================
// combine (128 thr, 4x8 tiles): stage1 grid 24 (L4+L4t, L3), stage2 grid 256 (L8t)
// ============================================================================
__global__ void __launch_bounds__(128) combine_kernel(int stage) {
    extern __shared__ float dynC[];
    float* Atd = dynC;            // 8192 floats
    float* Bn  = dynC + 8192;     // 4096 floats

    __shared__ float sred4[4];

    const int c = blockIdx.x;
    const int tid  = threadIdx.x;
    const int lane = tid & 31;
    const int w    = tid >> 5;
    const int jc   = tid & 7;
    const int rc   = tid >> 3;

    const float *Asrc_t, *Bsrc; int eIn;
    if (stage == 1) {
        if (c < 16) { Asrc_t = g_L2t + (c >> 2) * 4096; Bsrc = g_L2 + (c & 3) * 4096;
                      eIn = g_e2[c >> 2] + g_e2[c & 3]; }
        else        { const int v = c - 16;
                      Asrc_t = g_L2t + (v >> 1) * 4096; Bsrc = g_L1 + (v & 1) * 4096;
                      eIn = g_e2[v >> 1] + g_e1[v & 1]; }
    } else {
        Asrc_t = g_L4t + (c >> 4) * 4096; Bsrc = g_L4 + (c & 15) * 4096;
        eIn = g_e4[c >> 4] + g_e4[c & 15];
    }

    stage_dup128(Asrc_t, Atd);
    stage_nrm128(Bsrc, Bn);
    __syncthreads();

    float out[4][8];
    gemm4x8_dup(Atd, Bn, jc, rc, out);
    float mx = 0.f;
#pragma unroll
    for (int r = 0; r < 4; r++)
#pragma unroll
        for (int cc = 0; cc < 8; cc++) mx = fmaxf(mx, out[r][cc]);
    const float m = blockmax128(mx, sred4, lane, w);
    const int e = (__float_as_int(m) >> 23) - 127;
    const float sc = __int_as_float((127 - e) << 23);

    if (stage == 1) {
        if (c < 16) {
#pragma unroll
            for (int r = 0; r < 4; r++)
#pragma unroll
                for (int q = 0; q < 2; q++) {
                    float4 wv = make_float4(out[r][4 * q] * sc, out[r][4 * q + 1] * sc,
                                            out[r][4 * q + 2] * sc, out[r][4 * q + 3] * sc);
                    *(float4*)(g_L4 + c * 4096 + (4 * rc + r) * NS + 8 * jc + 4 * q) = wv;
                }
#pragma unroll
            for (int cc = 0; cc < 8; cc++) {
                float4 wv = make_float4(out[0][cc] * sc, out[1][cc] * sc,
                                        out[2][cc] * sc, out[3][cc] * sc);
                *(float4*)(g_L4t + c * 4096 + (8 * jc + cc) * NS + 4 * rc) = wv;
            }
            if (tid == 0) g_e4[c] = eIn + e;
        } else {
            const int v = c - 16;
#pragma unroll
            for (int r = 0; r < 4; r++)
#pragma unroll
                for (int q = 0; q < 2; q++) {
                    float4 wv = make_float4(out[r][4 * q] * sc, out[r][4 * q + 1] * sc,
                                            out[r][4 * q + 2] * sc, out[r][4 * q + 3] * sc);
                    *(float4*)(g_L3 + v * 4096 + (4 * rc + r) * NS + 8 * jc + 4 * q) = wv;
                }
            if (tid == 0) g_e3[v] = eIn + e;
        }
    } else {
#pragma unroll
        for (int cc = 0; cc < 8; cc++) {
            float4 wv = make_float4(out[0][cc] * sc, out[1][cc] * sc,
                                    out[2][cc] * sc, out[3][cc] * sc);
            *(float4*)(g_L8t + c * 4096 + (8 * jc + cc) * NS + 4 * rc) = wv;
        }
        if (tid == 0) g_e8[c] = eIn + e;
    }
}

// ============================================================================
// final (grid 2048, 128 thr, 4x8 tiles): P[code] = L8[code>>3] @ L3[code&7]
// normalize, permuted e4m3 encode + g_e11
// ============================================================================
__global__ void __launch_bounds__(128) final_kernel() {
    extern __shared__ float dynF[];
    float* Atd = dynF;            // 8192 floats
    float* Bn  = dynF + 8192;     // 4096 floats

    __shared__ float sred4[4];

    const int code = blockIdx.x;
    const int a = code >> 3;
    const int b = code & 7;
    const int tid  = threadIdx.x;
    const int lane = tid & 31;
    const int w    = tid >> 5;
    const int jc   = tid & 7;
    const int rc   = tid >> 3;

    stage_dup128(g_L8t + a * 4096, Atd);
    stage_nrm128(g_L3 + b * 4096, Bn);
    __syncthreads();

    // out[r][cc]: row k = 4rc+r (input state), col o = 8jc+cc
    float out[4][8];
    gemm4x8_dup(Atd, Bn, jc, rc, out);
    float mx = 0.f;
#pragma unroll
    for (int r = 0; r < 4; r++)
#pragma unroll
        for (int cc = 0; cc < 8; cc++) mx = fmaxf(mx, out[r][cc]);
    const float m = blockmax128(mx, sred4, lane, w);
    const int e = (__float_as_int(m) >> 23) - 127;
    const float sc = __int_as_float((127 - e) << 23);

    // e4m3 write: per col o = 8jc+cc, 4 consecutive k = 4rc..4rc+3 -> one u32
    const int k0 = 4 * rc;
#pragma unroll
    for (int cc = 0; cc < 8; cc++) {
        const int o = 8 * jc + cc;
        const unsigned p01 = f2_e4m3x2(out[1][cc] * sc, out[0][cc] * sc);
        const unsigned p23 = f2_e4m3x2(out[3][cc] * sc, out[2][cc] * sc);
        unsigned* dst = (unsigned*)((char*)g_Pt4 + (size_t)code * 4096
                        + ((o < 32 ? 0 : 4) + (k0 >> 4)) * 512
                        + (o & 31) * 16 + (k0 & 15));
        *dst = p01 | (p23 << 16);
    }
    if (tid == 0) g_e11[code] = g_e8[a] + g_e3[b] + e;
}

// ============================================================================
// main: one warp per element; inline ballot codes; fp8 table, half2 matvec
// (unchanged)
// ============================================================================
#define PREFETCH(MB, c)                                                       \
    {                                                                         \
        const uint4* __restrict__ tp = g_Pt4 + (size_t)(c) * 256 + lane;      \
        _Pragma("unroll")                                                     \
        for (int i = 0; i < 8; i++) MB[i] = tp[i * 32];                       \
    }

#define PROC8(u, av0, av1, acc)                                               \
    acc = __hfma2(e4m3x2_h2((unsigned short)(u).x),         as_h2((av0).x), acc); \
    acc = __hfma2(e4m3x2_h2((unsigned short)((u).x >> 16)), as_h2((av0).y), acc); \
    acc = __hfma2(e4m3x2_h2((unsigned short)(u).y),         as_h2((av0).z), acc); \
    acc = __hfma2(e4m3x2_h2((unsigned short)((u).y >> 16)), as_h2((av0).w), acc); \
    acc = __hfma2(e4m3x2_h2((unsigned short)(u).z),         as_h2((av1).x), acc); \
    acc = __hfma2(e4m3x2_h2((unsigned short)((u).z >> 16)), as_h2((av1).y), acc); \
    acc = __hfma2(e4m3x2_h2((unsigned short)(u).w),         as_h2((av1).z), acc); \
    acc = __hfma2(e4m3x2_h2((unsigned short)((u).w >> 16)), as_h2((av1).w), acc);

#define PACKSTORE(PP)                                                         \
    {                                                                         \
        const float ev = __shfl_sync(0xffffffffu, s_lo, 0);                   \
        int e = (__float_as_int(ev) >> 23) - 125;                             \
        e = max(-120, min(120, e));                                           \
        const float rsc = __int_as_float((127 - e) << 23);                    \
        s_lo *= rsc; s_hi *= rsc; ce += e;                                    \
        const float lo0 = __shfl_sync(0xffffffffu, s_lo, (2 * lane) & 31);    \
        const float lo1 = __shfl_sync(0xffffffffu, s_lo, (2 * lane + 1) & 31);\
        const float hi0 = __shfl_sync(0xffffffffu, s_hi, (2 * lane) & 31);    \
        const float hi1 = __shfl_sync(0xffffffffu, s_hi, (2 * lane + 1) & 31);\
        const float x0 = lane < 16 ? lo0 : hi0;                               \
        const float x1 = lane < 16 ? lo1 : hi1;                               \
        s_ah[wid][PP][lane] = __floats2half2_rn(x0, x1);                      \
        __syncwarp();                                                         \
    }

#define COMPUTE(MB, CODE)                                                     \
    {                                                                         \
        const uint4* __restrict__ ah = (const uint4*)s_ah[wid][p];            \
        uint4 au[8];                                                          \
        _Pragma("unroll")                                                     \
        for (int q = 0; q < 8; q++) au[q] = ah[q];                            \
        __half2 c0 = __float2half2_rn(0.f), c1 = c0, c2 = c0, c3 = c0;        \
        __half2 d0 = c0, d1 = c0, d2 = c0, d3 = c0;                           \
        PROC8(MB[0], au[0], au[1], c0)                                        \
        PROC8(MB[1], au[2], au[3], c1)                                        \
        PROC8(MB[2], au[4], au[5], c2)                                        \
        PROC8(MB[3], au[6], au[7], c3)                                        \
        PROC8(MB[4], au[0], au[1], d0)                                        \
        PROC8(MB[5], au[2], au[3], d1)                                        \
        PROC8(MB[6], au[4], au[5], d2)                                        \
        PROC8(MB[7], au[6], au[7], d3)                                        \
        const __half2 tc = __hadd2(__hadd2(c0, c1), __hadd2(c2, c3));         \
        const __half2 td = __hadd2(__hadd2(d0, d1), __hadd2(d2, d3));         \
        s_lo = __low2float(tc) + __high2float(tc);                            \
        s_hi = __low2float(td) + __high2float(td);                            \
        ce += g_e11[CODE];                                                    \
        p ^= 1;                                                               \
        PACKSTORE(p)                                                          \
    }

__device__ __forceinline__ int getcode(const unsigned* __restrict__ bw, int j) {
    const int base = 1 + LBLK * j;
    const unsigned lo = bw[base >> 5];
    const unsigned hi = bw[(base >> 5) + 1];
    return (int)(__brev(__funnelshift_r(lo, hi, base & 31)) >> 21);
}

__global__ void __launch_bounds__(128)
hmm_main_kernel(const int* __restrict__ y, float* __restrict__ outp) {
    __shared__ __align__(16) __half2 s_ah[4][2][32];
    __shared__ unsigned s_bw[4][34];

    const int tid  = threadIdx.x;
    const int lane = tid & 31;
    const int wid  = tid >> 5;
    const int b    = blockIdx.x * 4 + wid;
    const int* __restrict__ yrow = y + b * DIM;

#pragma unroll
    for (int ch = 0; ch < 32; ch++) {
        const unsigned w = __ballot_sync(0xffffffffu, yrow[ch * 32 + lane]);
        if (lane == 0) s_bw[wid][ch] = w;
    }
    if (lane == 0) { s_bw[wid][32] = 0u; s_bw[wid][33] = 0u; }
    __syncwarp();
    const unsigned* __restrict__ bw = s_bw[wid];

    const int y0 = (int)(bw[0] & 1u);
    float s_lo = g_Pi[lane]      * (y0 ? g_E1[lane]      : g_E0[lane]);
    float s_hi = g_Pi[lane + 32] * (y0 ? g_E1[lane + 32] : g_E0[lane + 32]);

    int ce = 0, p = 0;
    PACKSTORE(0)

    uint4 mA[8], mB[8];
    int cA = getcode(bw, 0), cB;
    PREFETCH(mA, cA)

    for (int jj = 0; jj < 92; jj += 2) {
        cB = getcode(bw, jj + 1);
        PREFETCH(mB, cB)
        COMPUTE(mA, cA)
        cA = getcode(bw, jj + 2);
        PREFETCH(mA, cA)
        COMPUTE(mB, cB)
    }
    COMPUTE(mA, cA)   // j = 92 (prefetched at jj = 90)

    float v = s_lo + s_hi;
#pragma unroll
    for (int off = 16; off > 0; off >>= 1)
        v += __shfl_xor_sync(0xffffffffu, v, off);

    if (lane == 0) {
        const double logp = (double)logf(v) + (double)ce * 0.6931471805599453;
        atomicAdd(&g_acc, logp);
        __threadfence();
        const unsigned done = atomicAdd(&g_done, 1u);
        if (done == (unsigned)(BATCH - 1)) {
            outp[0] = (float)(g_acc * (1.0 / 4096.0));
        }
    }
}

extern "C" void kernel_launch(void* const* d_in, const int* in_sizes, int n_in,
                              void* d_out, int out_size) {
    const int*   y  = (const int*)  d_in[0];
    const float* Tr = (const float*)d_in[1];
    const float* Em = (const float*)d_in[2];
    const float* Pi = (const float*)d_in[3];

    cudaFuncSetAttribute(prep_kernel,
        cudaFuncAttributeMaxDynamicSharedMemorySize, 67584);
    cudaFuncSetAttribute(combine_kernel,
        cudaFuncAttributeMaxDynamicSharedMemorySize, 49152);
    cudaFuncSetAttribute(final_kernel,
        cudaFuncAttributeMaxDynamicSharedMemorySize, 49152);

    prep_kernel<<<1, 1024, 67584>>>(Tr, Em, Pi);
    combine_kernel<<<24, 128, 49152>>>(1);    // L4 (+L4t) and L3
    combine_kernel<<<256, 128, 49152>>>(2);   // L8t
    final_kernel<<<2048, 128, 49152>>>();     // fp8 table + e11 (4x8 tiles)
    hmm_main_kernel<<<BATCH / 4, 128>>>(y, (float*)d_out);
}

// round 15
// speedup vs baseline: 1.1500x; 1.1500x over previous
#include <cuda_runtime.h>
#include <cuda_bf16.h>
#include <cuda_fp16.h>

#define BATCH 4096
#define DIM   1024
#define NS    64
#define LBLK  11
#define NCODE 2048

typedef unsigned long long u64;

// ---- device-global scratch (static; no runtime alloc) ----
__device__ float  g_E0[NS], g_E1[NS], g_Pi[NS];
__device__ float  g_L1[2 * NS * NS];                  // normal [k][o]
__device__ float  g_L2[4 * NS * NS],  g_L2t[4 * NS * NS];
__device__ float  g_L3[8 * NS * NS];                  // L3[v] = L2[v>>1] @ L1[v&1]
__device__ float  g_L4[16 * NS * NS], g_L4t[16 * NS * NS];
__device__ float  g_L8t[256 * NS * NS];               // only transposed needed
__device__ int    g_e1[2], g_e2[4], g_e3[8], g_e4[16], g_e8[256], g_e11[NCODE];
// fp8 e4m3 table, permuted: byte(c,o,k) = c*4096 + ((o<32?0:4)+(k>>4))*512 + (o&31)*16 + (k&15)
__device__ uint4  g_Pt4[NCODE * 256];    // 8 MB
__device__ double g_acc;
__device__ unsigned g_done;

// ---- packed helpers ----
__device__ __forceinline__ u64 pk2(float lo, float hi) {
    u64 r; asm("mov.b64 %0, {%1,%2};" : "=l"(r) : "f"(lo), "f"(hi)); return r;
}
__device__ __forceinline__ void upk2(u64 v, float &lo, float &hi) {
    asm("mov.b64 {%0,%1}, %2;" : "=f"(lo), "=f"(hi) : "l"(v));
}
__device__ __forceinline__ u64 fma2(u64 a, u64 b, u64 c) {
    u64 d; asm("fma.rn.f32x2 %0, %1, %2, %3;" : "=l"(d) : "l"(a), "l"(b), "l"(c)); return d;
}
__device__ __forceinline__ unsigned short f2_e4m3x2(float hi, float lo) {
    unsigned short r;
    asm("cvt.rn.satfinite.e4m3x2.f32 %0, %1, %2;" : "=h"(r) : "f"(hi), "f"(lo));
    return r;
}
__device__ __forceinline__ __half2 e4m3x2_h2(unsigned short s) {
    unsigned r;
    asm("cvt.rn.f16x2.e4m3x2 %0, %1;" : "=r"(r) : "h"(s));
    return *(__half2*)&r;
}
__device__ __forceinline__ __half2 as_h2(unsigned w) { return *(__half2*)&w; }

// ---- classic 4x4 GEMM (prep L2 stage only; A transposed, not duplicated) ----
__device__ __forceinline__ void gemm4x4(const float* __restrict__ At, int strideF,
                                        const float* __restrict__ B,
                                        int jc, int rc, float out[4][4]) {
    u64 acc[4][2];
#pragma unroll
    for (int r = 0; r < 4; r++) { acc[r][0] = 0ull; acc[r][1] = 0ull; }
#pragma unroll 16
    for (int k = 0; k < NS; k++) {
        const float4 av = *(const float4*)(At + k * strideF + 4 * rc);
        const float4 bv = *(const float4*)(B  + k * NS      + 4 * jc);
        const u64 c01 = ((const u64*)&bv)[0];
        const u64 c23 = ((const u64*)&bv)[1];
        const u64 a0 = pk2(av.x, av.x), a1 = pk2(av.y, av.y);
        const u64 a2 = pk2(av.z, av.z), a3 = pk2(av.w, av.w);
        acc[0][0] = fma2(c01, a0, acc[0][0]); acc[0][1] = fma2(c23, a0, acc[0][1]);
        acc[1][0] = fma2(c01, a1, acc[1][0]); acc[1][1] = fma2(c23, a1, acc[1][1]);
        acc[2][0] = fma2(c01, a2, acc[2][0]); acc[2][1] = fma2(c23, a2, acc[2][1]);
        acc[3][0] = fma2(c01, a3, acc[3][0]); acc[3][1] = fma2(c23, a3, acc[3][1]);
    }
#pragma unroll
    for (int r = 0; r < 4; r++) {
        upk2(acc[r][0], out[r][0], out[r][1]);
        upk2(acc[r][1], out[r][2], out[r][3]);
    }
}

// ---- duplicated-A 4x4 GEMM: Atd[k*128 + 2r] = Atd[k*128 + 2r+1] = A[r][k] ----
__device__ __forceinline__ void gemm4x4_dup(const float* __restrict__ Atd,
                                            const float* __restrict__ B,
                                            int jc, int rc, float out[4][4]) {
    u64 acc[4][2];
#pragma unroll
    for (int r = 0; r < 4; r++) { acc[r][0] = 0ull; acc[r][1] = 0ull; }
#pragma unroll 16
    for (int k = 0; k < NS; k++) {
        const ulonglong2 a01 = *(const ulonglong2*)(Atd + k * 128 + 8 * rc);
        const ulonglong2 a23 = *(const ulonglong2*)(Atd + k * 128 + 8 * rc + 4);
        const float4 bv = *(const float4*)(B + k * NS + 4 * jc);
        const u64 c01 = ((const u64*)&bv)[0];
        const u64 c23 = ((const u64*)&bv)[1];
        acc[0][0] = fma2(c01, a01.x, acc[0][0]); acc[0][1] = fma2(c23, a01.x, acc[0][1]);
        acc[1][0] = fma2(c01, a01.y, acc[1][0]); acc[1][1] = fma2(c23, a01.y, acc[1][1]);
        acc[2][0] = fma2(c01, a23.x, acc[2][0]); acc[2][1] = fma2(c23, a23.x, acc[2][1]);
        acc[3][0] = fma2(c01, a23.y, acc[3][0]); acc[3][1] = fma2(c23, a23.y, acc[3][1]);
    }
#pragma unroll
    for (int r = 0; r < 4; r++) {
        upk2(acc[r][0], out[r][0], out[r][1]);
        upk2(acc[r][1], out[r][2], out[r][3]);
    }
}

__device__ __forceinline__ void stage_dup(const float* __restrict__ src_t,
                                          float* __restrict__ dst) {
    const int tid = threadIdx.x;
#pragma unroll
    for (int i = 0; i < 4; i++) {
        const int f  = tid + 256 * i;
        const float4 v = ((const float4*)src_t)[f];
        const int k  = f >> 4, r4 = (f & 15) * 4;
        float4* d = (float4*)(dst + k * 128 + 2 * r4);
        d[0] = make_float4(v.x, v.x, v.y, v.y);
        d[1] = make_float4(v.z, v.z, v.w, v.w);
    }
}
__device__ __forceinline__ void stage_nrm(const float* __restrict__ src,
                                          float* __restrict__ dst) {
    const int tid = threadIdx.x;
#pragma unroll
    for (int i = 0; i < 4; i++)
        ((float4*)dst)[tid + 256 * i] = ((const float4*)src)[tid + 256 * i];
}

// ============================================================================
// prep: softmaxes + L1 + L2 in ONE kernel (unchanged from R10)
// ============================================================================
__global__ void __launch_bounds__(1024)
prep_kernel(const float* __restrict__ Tr,
            const float* __restrict__ Em,
            const float* __restrict__ Pi) {
    extern __shared__ float dynP[];
    float* sL1n = dynP;
    float* sL1t = dynP + 8192;

    __shared__ float rowm[NS], rowinv[NS];
    __shared__ float sE[2][NS];
    __shared__ float sred[32];
    __shared__ float sbcA[4];
    __shared__ int   seiA[4];

    const int tid  = threadIdx.x;
    const int lane = tid & 31;
    const int w    = tid >> 5;

    if (tid == 0) { g_acc = 0.0; g_done = 0u; }

#pragma unroll
    for (int rr = 0; rr < 2; rr++) {
        const int r = w + rr * 32;
        const float v0 = Tr[r * NS + lane];
        const float v1 = Tr[r * NS + lane + 32];
        float m = fmaxf(v0, v1);
#pragma unroll
        for (int off = 16; off > 0; off >>= 1)
            m = fmaxf(m, __shfl_xor_sync(0xffffffffu, m, off));
        const float e0 = expf(v0 - m), e1v = expf(v1 - m);
        float s = e0 + e1v;
#pragma unroll
        for (int off = 16; off > 0; off >>= 1)
            s += __shfl_xor_sync(0xffffffffu, s, off);
        if (lane == 0) { rowm[r] = m; rowinv[r] = 1.f / s; }
    }
    if (tid < NS) {
        const float a = Em[tid * 2 + 0], b2 = Em[tid * 2 + 1];
        const float mm = fmaxf(a, b2);
        const float ea = expf(a - mm), eb = expf(b2 - mm);
        const float is = 1.f / (ea + eb);
        sE[0][tid] = ea * is;  sE[1][tid] = eb * is;
        g_E0[tid] = ea * is;   g_E1[tid] = eb * is;
    }
    if (w == 1) {
        const float v0 = Pi[lane], v1 = Pi[lane + 32];
        float m = fmaxf(v0, v1);
#pragma unroll
        for (int off = 16; off > 0; off >>= 1)
            m = fmaxf(m, __shfl_xor_sync(0xffffffffu, m, off));
        const float e0 = expf(v0 - m), e1v = expf(v1 - m);
        float s = e0 + e1v;
#pragma unroll
        for (int off = 16; off > 0; off >>= 1)
            s += __shfl_xor_sync(0xffffffffu, s, off);
        const float inv = 1.f / s;
        g_Pi[lane] = e0 * inv;  g_Pi[lane + 32] = e1v * inv;
    }
    __syncthreads();

    for (int y = 0; y < 2; y++) {
        float vv[4], vmax = 0.f;
#pragma unroll
        for (int i = 0; i < 4; i++) {
            const int idx = tid + i * 1024;
            const int k = idx >> 6, o = idx & 63;
            const float v = expf(Tr[idx] - rowm[k]) * rowinv[k] * sE[y][o];
            vv[i] = v; vmax = fmaxf(vmax, v);
        }
#pragma unroll
        for (int off = 16; off > 0; off >>= 1)
            vmax = fmaxf(vmax, __shfl_xor_sync(0xffffffffu, vmax, off));
        if (lane == 0) sred[w] = vmax;
        __syncthreads();
        if (tid < 32) {
            float m = sred[lane];
#pragma unroll
            for (int off = 16; off > 0; off >>= 1)
                m = fmaxf(m, __shfl_xor_sync(0xffffffffu, m, off));
            if (lane == 0) {
                const int e = (__float_as_int(m) >> 23) - 127;
                seiA[y] = e;  g_e1[y] = e;
                sbcA[y] = __int_as_float((127 - e) << 23);
            }
        }
        __syncthreads();
        const float sc = sbcA[y];
#pragma unroll
        for (int i = 0; i < 4; i++) {
            const int idx = tid + i * 1024;
            const int k = idx >> 6, o = idx & 63;
            const float v = vv[i] * sc;
            sL1n[y * 4096 + idx]         = v;
            sL1t[y * 4352 + o * 68 + k]  = v;
            g_L1[y * 4096 + idx]         = v;
        }
        __syncthreads();
    }

    {
        const int g    = tid >> 8;
        const int gtid = tid & 255;
        const int jc   = gtid & 15;
        const int rc   = gtid >> 4;
        float out[4][4];
        gemm4x4(sL1t + (g >> 1) * 4352, 68, sL1n + (g & 1) * 4096, jc, rc, out);
        float mx = 0.f;
#pragma unroll
        for (int r = 0; r < 4; r++)
#pragma unroll
            for (int c = 0; c < 4; c++) mx = fmaxf(mx, out[r][c]);
#pragma unroll
        for (int off = 16; off > 0; off >>= 1)
            mx = fmaxf(mx, __shfl_xor_sync(0xffffffffu, mx, off));
        if (lane == 0) sred[w] = mx;
        __syncthreads();
        if (tid < 4) {
            float m = sred[8 * tid];
#pragma unroll
            for (int q = 1; q < 8; q++) m = fmaxf(m, sred[8 * tid + q]);
            const int e = (__float_as_int(m) >> 23) - 127;
            sbcA[tid] = __int_as_float((127 - e) << 23);
            g_e2[tid] = seiA[tid >> 1] + seiA[tid & 1] + e;
        }
        __syncthreads();
        const float sc = sbcA[g];
#pragma unroll
        for (int r = 0; r < 4; r++) {
            float4 wv = make_float4(out[r][0] * sc, out[r][1] * sc,
                                    out[r][2] * sc, out[r][3] * sc);
            *(float4*)(g_L2 + g * 4096 + (4 * rc + r) * NS + 4 * jc) = wv;
        }
#pragma unroll
        for (int c = 0; c < 4; c++) {
            float4 wv = make_float4(out[0][c] * sc, out[1][c] * sc,
                                    out[2][c] * sc, out[3][c] * sc);
            *(float4*)(g_L2t + g * 4096 + (4 * jc + c) * NS + 4 * rc) = wv;
        }
    }
}

// ============================================================================
// combine (R10 version): stage1 grid 24 (L4+L4t, L3), stage2 grid 256 (L8t)
// ============================================================================
__global__ void __launch_bounds__(256) combine_kernel(int stage) {
    extern __shared__ float dynC[];
    float* Atd = dynC;
    float* Bn  = dynC + 8192;

    __shared__ float sred[8];
    __shared__ float sbc;
    __shared__ int   sei;

    const int c = blockIdx.x;
    const int tid  = threadIdx.x;
    const int lane = tid & 31;
    const int w    = tid >> 5;
    const int jc   = tid & 15;
    const int rc   = tid >> 4;

    const float *Asrc_t, *Bsrc; int eIn;
    if (stage == 1) {
        if (c < 16) { Asrc_t = g_L2t + (c >> 2) * 4096; Bsrc = g_L2 + (c & 3) * 4096;
                      eIn = g_e2[c >> 2] + g_e2[c & 3]; }
        else        { const int v = c - 16;
                      Asrc_t = g_L2t + (v >> 1) * 4096; Bsrc = g_L1 + (v & 1) * 4096;
                      eIn = g_e2[v >> 1] + g_e1[v & 1]; }
    } else {
        Asrc_t = g_L4t + (c >> 4) * 4096; Bsrc = g_L4 + (c & 15) * 4096;
        eIn = g_e4[c >> 4] + g_e4[c & 15];
    }

    stage_dup(Asrc_t, Atd);
    stage_nrm(Bsrc, Bn);
    __syncthreads();

    float out[4][4];
    gemm4x4_dup(Atd, Bn, jc, rc, out);
    float mx = 0.f;
#pragma unroll
    for (int r = 0; r < 4; r++)
#pragma unroll
        for (int cc = 0; cc < 4; cc++) mx = fmaxf(mx, out[r][cc]);
#pragma unroll
    for (int off = 16; off > 0; off >>= 1)
        mx = fmaxf(mx, __shfl_xor_sync(0xffffffffu, mx, off));
    if (lane == 0) sred[w] = mx;
    __syncthreads();
    if (tid == 0) {
        float m = sred[0];
#pragma unroll
        for (int q = 1; q < 8; q++) m = fmaxf(m, sred[q]);
        const int e = (__float_as_int(m) >> 23) - 127;
        sbc = __int_as_float((127 - e) << 23);
        sei = e;
    }
    __syncthreads();
    const float sc = sbc;

    if (stage == 1) {
        if (c < 16) {
#pragma unroll
            for (int r = 0; r < 4; r++) {
                float4 wv = make_float4(out[r][0] * sc, out[r][1] * sc,
                                        out[r][2] * sc, out[r][3] * sc);
                *(float4*)(g_L4 + c * 4096 + (4 * rc + r) * NS + 4 * jc) = wv;
            }
#pragma unroll
            for (int cc = 0; cc < 4; cc++) {
                float4 wv = make_float4(out[0][cc] * sc, out[1][cc] * sc,
                                        out[2][cc] * sc, out[3][cc] * sc);
                *(float4*)(g_L4t + c * 4096 + (4 * jc + cc) * NS + 4 * rc) = wv;
            }
            if (tid == 0) g_e4[c] = eIn + sei;
        } else {
            const int v = c - 16;
#pragma unroll
            for (int r = 0; r < 4; r++) {
                float4 wv = make_float4(out[r][0] * sc, out[r][1] * sc,
                                        out[r][2] * sc, out[r][3] * sc);
                *(float4*)(g_L3 + v * 4096 + (4 * rc + r) * NS + 4 * jc) = wv;
            }
            if (tid == 0) g_e3[v] = eIn + sei;
        }
    } else {
#pragma unroll
        for (int cc = 0; cc < 4; cc++) {
            float4 wv = make_float4(out[0][cc] * sc, out[1][cc] * sc,
                                    out[2][cc] * sc, out[3][cc] * sc);
            *(float4*)(g_L8t + c * 4096 + (4 * jc + cc) * NS + 4 * rc) = wv;
        }
        if (tid == 0) g_e8[c] = eIn + sei;
    }
}

// ============================================================================
// final (R10 version, grid 2048): P = L8[code>>3] @ L3[code&7]; e4m3 encode
// ============================================================================
__global__ void __launch_bounds__(256) final_kernel() {
    extern __shared__ float dynF[];
    float* Atd = dynF;            // 8192 floats
    float* Bn  = dynF + 8192;     // 4096 floats

    __shared__ float sred[8];
    __shared__ float sbc;
    __shared__ int   sei;

    const int code = blockIdx.x;
    const int a = code >> 3;
    const int b = code & 7;
    const int tid  = threadIdx.x;
    const int lane = tid & 31;
    const int w    = tid >> 5;
    const int jc   = tid & 15;
    const int rc   = tid >> 4;

    stage_dup(g_L8t + a * 4096, Atd);
    stage_nrm(g_L3 + b * 4096, Bn);
    __syncthreads();

    float out[4][4];
    gemm4x4_dup(Atd, Bn, jc, rc, out);
    float mx = 0.f;
#pragma unroll
    for (int r = 0; r < 4; r++)
#pragma unroll
        for (int cc = 0; cc < 4; cc++) mx = fmaxf(mx, out[r][cc]);
#pragma unroll
    for (int off = 16; off > 0; off >>= 1)
        mx = fmaxf(mx, __shfl_xor_sync(0xffffffffu, mx, off));
    if (lane == 0) sred[w] = mx;
    __syncthreads();
    if (tid == 0) {
        float m = sred[0];
#pragma unroll
        for (int q = 1; q < 8; q++) m = fmaxf(m, sred[q]);
        const int e = (__float_as_int(m) >> 23) - 127;
        sbc = __int_as_float((127 - e) << 23);
        sei = e;
    }
    __syncthreads();
    const float sc = sbc;

    const int k0 = 4 * rc;
#pragma unroll
    for (int cc = 0; cc < 4; cc++) {
        const int o = 4 * jc + cc;
        const unsigned p01 = f2_e4m3x2(out[1][cc] * sc, out[0][cc] * sc);
        const unsigned p23 = f2_e4m3x2(out[3][cc] * sc, out[2][cc] * sc);
        unsigned* dst = (unsigned*)((char*)g_Pt4 + (size_t)code * 4096
                        + ((o < 32 ? 0 : 4) + (k0 >> 4)) * 512
                        + (o & 31) * 16 + (k0 & 15));
        *dst = p01 | (p23 << 16);
    }
    if (tid == 0) g_e11[code] = g_e8[a] + g_e3[b] + sei;
}

// ============================================================================
// main: one warp per element; depth-2 prefetch pipeline (triple buffer)
// ============================================================================
#define PREFETCH(MB, c)                                                       \
    {                                                                         \
        const uint4* __restrict__ tp = g_Pt4 + (size_t)(c) * 256 + lane;      \
        _Pragma("unroll")                                                     \
        for (int i = 0; i < 8; i++) MB[i] = tp[i * 32];                       \
    }

#define PROC8(u, av0, av1, acc)                                               \
    acc = __hfma2(e4m3x2_h2((unsigned short)(u).x),         as_h2((av0).x), acc); \
    acc = __hfma2(e4m3x2_h2((unsigned short)((u).x >> 16)), as_h2((av0).y), acc); \
    acc = __hfma2(e4m3x2_h2((unsigned short)(u).y),         as_h2((av0).z), acc); \
    acc = __hfma2(e4m3x2_h2((unsigned short)((u).y >> 16)), as_h2((av0).w), acc); \
    acc = __hfma2(e4m3x2_h2((unsigned short)(u).z),         as_h2((av1).x), acc); \
    acc = __hfma2(e4m3x2_h2((unsigned short)((u).z >> 16)), as_h2((av1).y), acc); \
    acc = __hfma2(e4m3x2_h2((unsigned short)(u).w),         as_h2((av1).z), acc); \
    acc = __hfma2(e4m3x2_h2((unsigned short)((u).w >> 16)), as_h2((av1).w), acc);

#define PACKSTORE(PP)                                                         \
    {                                                                         \
        const float ev = __shfl_sync(0xffffffffu, s_lo, 0);                   \
        int e = (__float_as_int(ev) >> 23) - 125;                             \
        e = max(-120, min(120, e));                                           \
        const float rsc = __int_as_float((127 - e) << 23);                    \
        s_lo *= rsc; s_hi *= rsc; ce += e;                                    \
        const float lo0 = __shfl_sync(0xffffffffu, s_lo, (2 * lane) & 31);    \
        const float lo1 = __shfl_sync(0xffffffffu, s_lo, (2 * lane + 1) & 31);\
        const float hi0 = __shfl_sync(0xffffffffu, s_hi, (2 * lane) & 31);    \
        const float hi1 = __shfl_sync(0xffffffffu, s_hi, (2 * lane + 1) & 31);\
        const float x0 = lane < 16 ? lo0 : hi0;                               \
        const float x1 = lane < 16 ? lo1 : hi1;                               \
        s_ah[wid][PP][lane] = __floats2half2_rn(x0, x1);                      \
        __syncwarp();                                                         \
    }

#define COMPUTE(MB, CODE)                                                     \
    {                                                                         \
        const uint4* __restrict__ ah = (const uint4*)s_ah[wid][p];            \
        uint4 au[8];                                                          \
        _Pragma("unroll")                                                     \
        for (int q = 0; q < 8; q++) au[q] = ah[q];                            \
        __half2 h0 = __float2half2_rn(0.f), h1 = h0, h2 = h0, h3 = h0;        \
        __half2 g0 = h0, g1 = h0, g2 = h0, g3 = h0;                           \
        PROC8(MB[0], au[0], au[1], h0)                                        \
        PROC8(MB[1], au[2], au[3], h1)                                        \
        PROC8(MB[2], au[4], au[5], h2)                                        \
        PROC8(MB[3], au[6], au[7], h3)                                        \
        PROC8(MB[4], au[0], au[1], g0)                                        \
        PROC8(MB[5], au[2], au[3], g1)                                        \
        PROC8(MB[6], au[4], au[5], g2)                                        \
        PROC8(MB[7], au[6], au[7], g3)                                        \
        const __half2 tc = __hadd2(__hadd2(h0, h1), __hadd2(h2, h3));         \
        const __half2 td = __hadd2(__hadd2(g0, g1), __hadd2(g2, g3));         \
        s_lo = __low2float(tc) + __high2float(tc);                            \
        s_hi = __low2float(td) + __high2float(td);                            \
        ce += g_e11[CODE];                                                    \
        p ^= 1;                                                               \
        PACKSTORE(p)                                                          \
    }

// NOTE: getcode(j) for j >= 93 reads the zeroed pad words (bw[32],bw[33]) and
// returns code 0 — a safe, in-bounds prefetch target for pipeline overrun.
__device__ __forceinline__ int getcode(const unsigned* __restrict__ bw, int j) {
    const int base = 1 + LBLK * j;
    const unsigned lo = bw[base >> 5];
    const unsigned hi = bw[(base >> 5) + 1];
    return (int)(__brev(__funnelshift_r(lo, hi, base & 31)) >> 21);
}

__global__ void __launch_bounds__(128)
hmm_main_kernel(const int* __restrict__ y, float* __restrict__ outp) {
    __shared__ __align__(16) __half2 s_ah[4][2][32];
    __shared__ unsigned s_bw[4][34];

    const int tid  = threadIdx.x;
    const int lane = tid & 31;
    const int wid  = tid >> 5;
    const int b    = blockIdx.x * 4 + wid;
    const int* __restrict__ yrow = y + b * DIM;

#pragma unroll
    for (int ch = 0; ch < 32; ch++) {
        const unsigned w = __ballot_sync(0xffffffffu, yrow[ch * 32 + lane]);
        if (lane == 0) s_bw[wid][ch] = w;
    }
    if (lane == 0) { s_bw[wid][32] = 0u; s_bw[wid][33] = 0u; }
    __syncwarp();
    const unsigned* __restrict__ bw = s_bw[wid];

    const int y0 = (int)(bw[0] & 1u);
    float s_lo = g_Pi[lane]      * (y0 ? g_E1[lane]      : g_E0[lane]);
    float s_hi = g_Pi[lane + 32] * (y0 ? g_E1[lane + 32] : g_E0[lane + 32]);

    int ce = 0, p = 0;
    PACKSTORE(0)

    // depth-2 software pipeline: 93 codes = 3 x 31
    uint4 m0[8], m1[8], m2[8];
    int cc0 = getcode(bw, 0);
    int cc1 = getcode(bw, 1);
    int cc2;
    PREFETCH(m0, cc0)
    PREFETCH(m1, cc1)

    for (int j = 0; j < 93; j += 3) {
        cc2 = getcode(bw, j + 2);
        PREFETCH(m2, cc2)
        COMPUTE(m0, cc0)
        cc0 = getcode(bw, j + 3);    // overrun at j=90 -> j+3=93 reads zero pad
        PREFETCH(m0, cc0)
        COMPUTE(m1, cc1)
        cc1 = getcode(bw, j + 4);    // j+4 <= 94: safe (pad)
        PREFETCH(m1, cc1)
        COMPUTE(m2, cc2)
    }

    float v = s_lo + s_hi;
#pragma unroll
    for (int off = 16; off > 0; off >>= 1)
        v += __shfl_xor_sync(0xffffffffu, v, off);

    if (lane == 0) {
        const double logp = (double)logf(v) + (double)ce * 0.6931471805599453;
        atomicAdd(&g_acc, logp);
        __threadfence();
        const unsigned done = atomicAdd(&g_done, 1u);
        if (done == (unsigned)(BATCH - 1)) {
            outp[0] = (float)(g_acc * (1.0 / 4096.0));
        }
    }
}

extern "C" void kernel_launch(void* const* d_in, const int* in_sizes, int n_in,
                              void* d_out, int out_size) {
    const int*   y  = (const int*)  d_in[0];
    const float* Tr = (const float*)d_in[1];
    const float* Em = (const float*)d_in[2];
    const float* Pi = (const float*)d_in[3];

    cudaFuncSetAttribute(prep_kernel,
        cudaFuncAttributeMaxDynamicSharedMemorySize, 67584);
    cudaFuncSetAttribute(combine_kernel,
        cudaFuncAttributeMaxDynamicSharedMemorySize, 49152);
    cudaFuncSetAttribute(final_kernel,
        cudaFuncAttributeMaxDynamicSharedMemorySize, 49152);

    prep_kernel<<<1, 1024, 67584>>>(Tr, Em, Pi);
    combine_kernel<<<24, 256, 49152>>>(1);    // L4 (+L4t) and L3
    combine_kernel<<<256, 256, 49152>>>(2);   // L8t
    final_kernel<<<2048, 256, 49152>>>();     // fp8 table + e11
    hmm_main_kernel<<<BATCH / 4, 128>>>(y, (float*)d_out);
}

// round 16
// speedup vs baseline: 1.2056x; 1.0484x over previous
#include <cuda_runtime.h>
#include <cuda_bf16.h>
#include <cuda_fp16.h>
#include <mma.h>

#define BATCH 4096
#define DIM   1024
#define NS    64
#define LBLK  11
#define NCODE 2048

typedef unsigned long long u64;
using namespace nvcuda;

// ---- device-global scratch (static; no runtime alloc) ----
__device__ float  g_E0[NS], g_E1[NS], g_Pi[NS];
__device__ float  g_L1[2 * NS * NS];                  // normal [k][o]
__device__ float  g_L2[4 * NS * NS],  g_L2t[4 * NS * NS];
__device__ float  g_L3[8 * NS * NS];                  // L3[v] = L2[v>>1] @ L1[v&1]
__device__ float  g_L4[16 * NS * NS], g_L4t[16 * NS * NS];
__device__ float  g_L8n[256 * NS * NS];               // NORMAL layout (wmma A)
__device__ int    g_e1[2], g_e2[4], g_e3[8], g_e4[16], g_e8[256], g_e11[NCODE];
// fp8 e4m3 table, permuted: byte(c,o,k) = c*4096 + ((o<32?0:4)+(k>>4))*512 + (o&31)*16 + (k&15)
__device__ uint4  g_Pt4[NCODE * 256];    // 8 MB
__device__ double g_acc;
__device__ unsigned g_done;

// ---- packed helpers ----
__device__ __forceinline__ u64 pk2(float lo, float hi) {
    u64 r; asm("mov.b64 %0, {%1,%2};" : "=l"(r) : "f"(lo), "f"(hi)); return r;
}
__device__ __forceinline__ void upk2(u64 v, float &lo, float &hi) {
    asm("mov.b64 {%0,%1}, %2;" : "=f"(lo), "=f"(hi) : "l"(v));
}
__device__ __forceinline__ u64 fma2(u64 a, u64 b, u64 c) {
    u64 d; asm("fma.rn.f32x2 %0, %1, %2, %3;" : "=l"(d) : "l"(a), "l"(b), "l"(c)); return d;
}
__device__ __forceinline__ unsigned short f2_e4m3x2(float hi, float lo) {
    unsigned short r;
    asm("cvt.rn.satfinite.e4m3x2.f32 %0, %1, %2;" : "=h"(r) : "f"(hi), "f"(lo));
    return r;
}
__device__ __forceinline__ __half2 e4m3x2_h2(unsigned short s) {
    unsigned r;
    asm("cvt.rn.f16x2.e4m3x2 %0, %1;" : "=r"(r) : "h"(s));
    return *(__half2*)&r;
}
__device__ __forceinline__ __half2 as_h2(unsigned w) { return *(__half2*)&w; }

// ---- classic 4x4 GEMM (prep L2 stage only) ----
__device__ __forceinline__ void gemm4x4(const float* __restrict__ At, int strideF,
                                        const float* __restrict__ B,
                                        int jc, int rc, float out[4][4]) {
    u64 acc[4][2];
#pragma unroll
    for (int r = 0; r < 4; r++) { acc[r][0] = 0ull; acc[r][1] = 0ull; }
#pragma unroll 16
    for (int k = 0; k < NS; k++) {
        const float4 av = *(const float4*)(At + k * strideF + 4 * rc);
        const float4 bv = *(const float4*)(B  + k * NS      + 4 * jc);
        const u64 c01 = ((const u64*)&bv)[0];
        const u64 c23 = ((const u64*)&bv)[1];
        const u64 a0 = pk2(av.x, av.x), a1 = pk2(av.y, av.y);
        const u64 a2 = pk2(av.z, av.z), a3 = pk2(av.w, av.w);
        acc[0][0] = fma2(c01, a0, acc[0][0]); acc[0][1] = fma2(c23, a0, acc[0][1]);
        acc[1][0] = fma2(c01, a1, acc[1][0]); acc[1][1] = fma2(c23, a1, acc[1][1]);
        acc[2][0] = fma2(c01, a2, acc[2][0]); acc[2][1] = fma2(c23, a2, acc[2][1]);
        acc[3][0] = fma2(c01, a3, acc[3][0]); acc[3][1] = fma2(c23, a3, acc[3][1]);
    }
#pragma unroll
    for (int r = 0; r < 4; r++) {
        upk2(acc[r][0], out[r][0], out[r][1]);
        upk2(acc[r][1], out[r][2], out[r][3]);
    }
}

// ---- duplicated-A 4x4 GEMM: Atd[k*128 + 2r] = Atd[k*128 + 2r+1] = A[r][k] ----
__device__ __forceinline__ void gemm4x4_dup(const float* __restrict__ Atd,
                                            const float* __restrict__ B,
                                            int jc, int rc, float out[4][4]) {
    u64 acc[4][2];
#pragma unroll
    for (int r = 0; r < 4; r++) { acc[r][0] = 0ull; acc[r][1] = 0ull; }
#pragma unroll 16
    for (int k = 0; k < NS; k++) {
        const ulonglong2 a01 = *(const ulonglong2*)(Atd + k * 128 + 8 * rc);
        const ulonglong2 a23 = *(const ulonglong2*)(Atd + k * 128 + 8 * rc + 4);
        const float4 bv = *(const float4*)(B + k * NS + 4 * jc);
        const u64 c01 = ((const u64*)&bv)[0];
        const u64 c23 = ((const u64*)&bv)[1];
        acc[0][0] = fma2(c01, a01.x, acc[0][0]); acc[0][1] = fma2(c23, a01.x, acc[0][1]);
        acc[1][0] = fma2(c01, a01.y, acc[1][0]); acc[1][1] = fma2(c23, a01.y, acc[1][1]);
        acc[2][0] = fma2(c01, a23.x, acc[2][0]); acc[2][1] = fma2(c23, a23.x, acc[2][1]);
        acc[3][0] = fma2(c01, a23.y, acc[3][0]); acc[3][1] = fma2(c23, a23.y, acc[3][1]);
    }
#pragma unroll
    for (int r = 0; r < 4; r++) {
        upk2(acc[r][0], out[r][0], out[r][1]);
        upk2(acc[r][1], out[r][2], out[r][3]);
    }
}

__device__ __forceinline__ void stage_dup(const float* __restrict__ src_t,
                                          float* __restrict__ dst) {
    const int tid = threadIdx.x;
#pragma unroll
    for (int i = 0; i < 4; i++) {
        const int f  = tid + 256 * i;
        const float4 v = ((const float4*)src_t)[f];
        const int k  = f >> 4, r4 = (f & 15) * 4;
        float4* d = (float4*)(dst + k * 128 + 2 * r4);
        d[0] = make_float4(v.x, v.x, v.y, v.y);
        d[1] = make_float4(v.z, v.z, v.w, v.w);
    }
}
__device__ __forceinline__ void stage_nrm(const float* __restrict__ src,
                                          float* __restrict__ dst) {
    const int tid = threadIdx.x;
#pragma unroll
    for (int i = 0; i < 4; i++)
        ((float4*)dst)[tid + 256 * i] = ((const float4*)src)[tid + 256 * i];
}

// ============================================================================
// prep: softmaxes + L1 + L2 in ONE kernel (unchanged)
// ============================================================================
__global__ void __launch_bounds__(1024)
prep_kernel(const float* __restrict__ Tr,
            const float* __restrict__ Em,
            const float* __restrict__ Pi) {
    extern __shared__ float dynP[];
    float* sL1n = dynP;
    float* sL1t = dynP + 8192;

    __shared__ float rowm[NS], rowinv[NS];
    __shared__ float sE[2][NS];
    __shared__ float sred[32];
    __shared__ float sbcA[4];
    __shared__ int   seiA[4];

    const int tid  = threadIdx.x;
    const int lane = tid & 31;
    const int w    = tid >> 5;

    if (tid == 0) { g_acc = 0.0; g_done = 0u; }

#pragma unroll
    for (int rr = 0; rr < 2; rr++) {
        const int r = w + rr * 32;
        const float v0 = Tr[r * NS + lane];
        const float v1 = Tr[r * NS + lane + 32];
        float m = fmaxf(v0, v1);
#pragma unroll
        for (int off = 16; off > 0; off >>= 1)
            m = fmaxf(m, __shfl_xor_sync(0xffffffffu, m, off));
        const float e0 = expf(v0 - m), e1v = expf(v1 - m);
        float s = e0 + e1v;
#pragma unroll
        for (int off = 16; off > 0; off >>= 1)
            s += __shfl_xor_sync(0xffffffffu, s, off);
        if (lane == 0) { rowm[r] = m; rowinv[r] = 1.f / s; }
    }
    if (tid < NS) {
        const float a = Em[tid * 2 + 0], b2 = Em[tid * 2 + 1];
        const float mm = fmaxf(a, b2);
        const float ea = expf(a - mm), eb = expf(b2 - mm);
        const float is = 1.f / (ea + eb);
        sE[0][tid] = ea * is;  sE[1][tid] = eb * is;
        g_E0[tid] = ea * is;   g_E1[tid] = eb * is;
    }
    if (w == 1) {
        const float v0 = Pi[lane], v1 = Pi[lane + 32];
        float m = fmaxf(v0, v1);
#pragma unroll
        for (int off = 16; off > 0; off >>= 1)
            m = fmaxf(m, __shfl_xor_sync(0xffffffffu, m, off));
        const float e0 = expf(v0 - m), e1v = expf(v1 - m);
        float s = e0 + e1v;
#pragma unroll
        for (int off = 16; off > 0; off >>= 1)
            s += __shfl_xor_sync(0xffffffffu, s, off);
        const float inv = 1.f / s;
        g_Pi[lane] = e0 * inv;  g_Pi[lane + 32] = e1v * inv;
    }
    __syncthreads();

    for (int y = 0; y < 2; y++) {
        float vv[4], vmax = 0.f;
#pragma unroll
        for (int i = 0; i < 4; i++) {
            const int idx = tid + i * 1024;
            const int k = idx >> 6, o = idx & 63;
            const float v = expf(Tr[idx] - rowm[k]) * rowinv[k] * sE[y][o];
            vv[i] = v; vmax = fmaxf(vmax, v);
        }
#pragma unroll
        for (int off = 16; off > 0; off >>= 1)
            vmax = fmaxf(vmax, __shfl_xor_sync(0xffffffffu, vmax, off));
        if (lane == 0) sred[w] = vmax;
        __syncthreads();
        if (tid < 32) {
            float m = sred[lane];
#pragma unroll
            for (int off = 16; off > 0; off >>= 1)
                m = fmaxf(m, __shfl_xor_sync(0xffffffffu, m, off));
            if (lane == 0) {
                const int e = (__float_as_int(m) >> 23) - 127;
                seiA[y] = e;  g_e1[y] = e;
                sbcA[y] = __int_as_float((127 - e) << 23);
            }
        }
        __syncthreads();
        const float sc = sbcA[y];
#pragma unroll
        for (int i = 0; i < 4; i++) {
            const int idx = tid + i * 1024;
            const int k = idx >> 6, o = idx & 63;
            const float v = vv[i] * sc;
            sL1n[y * 4096 + idx]         = v;
            sL1t[y * 4352 + o * 68 + k]  = v;
            g_L1[y * 4096 + idx]         = v;
        }
        __syncthreads();
    }

    {
        const int g    = tid >> 8;
        const int gtid = tid & 255;
        const int jc   = gtid & 15;
        const int rc   = gtid >> 4;
        float out[4][4];
        gemm4x4(sL1t + (g >> 1) * 4352, 68, sL1n + (g & 1) * 4096, jc, rc, out);
        float mx = 0.f;
#pragma unroll
        for (int r = 0; r < 4; r++)
#pragma unroll
            for (int c = 0; c < 4; c++) mx = fmaxf(mx, out[r][c]);
#pragma unroll
        for (int off = 16; off > 0; off >>= 1)
            mx = fmaxf(mx, __shfl_xor_sync(0xffffffffu, mx, off));
        if (lane == 0) sred[w] = mx;
        __syncthreads();
        if (tid < 4) {
            float m = sred[8 * tid];
#pragma unroll
            for (int q = 1; q < 8; q++) m = fmaxf(m, sred[8 * tid + q]);
            const int e = (__float_as_int(m) >> 23) - 127;
            sbcA[tid] = __int_as_float((127 - e) << 23);
            g_e2[tid] = seiA[tid >> 1] + seiA[tid & 1] + e;
        }
        __syncthreads();
        const float sc = sbcA[g];
#pragma unroll
        for (int r = 0; r < 4; r++) {
            float4 wv = make_float4(out[r][0] * sc, out[r][1] * sc,
                                    out[r][2] * sc, out[r][3] * sc);
            *(float4*)(g_L2 + g * 4096 + (4 * rc + r) * NS + 4 * jc) = wv;
        }
#pragma unroll
        for (int c = 0; c < 4; c++) {
            float4 wv = make_float4(out[0][c] * sc, out[1][c] * sc,
                                    out[2][c] * sc, out[3][c] * sc);
            *(float4*)(g_L2t + g * 4096 + (4 * jc + c) * NS + 4 * rc) = wv;
        }
    }
}

// ============================================================================
// combine: stage1 grid 24 (L4+L4t, L3), stage2 grid 256 (L8 NORMAL layout)
// ============================================================================
__global__ void __launch_bounds__(256) combine_kernel(int stage) {
    extern __shared__ float dynC[];
    float* Atd = dynC;
    float* Bn  = dynC + 8192;

    __shared__ float sred[8];
    __shared__ float sbc;
    __shared__ int   sei;

    const int c = blockIdx.x;
    const int tid  = threadIdx.x;
    const int lane = tid & 31;
    const int w    = tid >> 5;
    const int jc   = tid & 15;
    const int rc   = tid >> 4;

    const float *Asrc_t, *Bsrc; int eIn;
    if (stage == 1) {
        if (c < 16) { Asrc_t = g_L2t + (c >> 2) * 4096; Bsrc = g_L2 + (c & 3) * 4096;
                      eIn = g_e2[c >> 2] + g_e2[c & 3]; }
        else        { const int v = c - 16;
                      Asrc_t = g_L2t + (v >> 1) * 4096; Bsrc = g_L1 + (v & 1) * 4096;
                      eIn = g_e2[v >> 1] + g_e1[v & 1]; }
    } else {
        Asrc_t = g_L4t + (c >> 4) * 4096; Bsrc = g_L4 + (c & 15) * 4096;
        eIn = g_e4[c >> 4] + g_e4[c & 15];
    }

    stage_dup(Asrc_t, Atd);
    stage_nrm(Bsrc, Bn);
    __syncthreads();

    float out[4][4];
    gemm4x4_dup(Atd, Bn, jc, rc, out);
    float mx = 0.f;
#pragma unroll
    for (int r = 0; r < 4; r++)
#pragma unroll
        for (int cc = 0; cc < 4; cc++) mx = fmaxf(mx, out[r][cc]);
#pragma unroll
    for (int off = 16; off > 0; off >>= 1)
        mx = fmaxf(mx, __shfl_xor_sync(0xffffffffu, mx, off));
    if (lane == 0) sred[w] = mx;
    __syncthreads();
    if (tid == 0) {
        float m = sred[0];
#pragma unroll
        for (int q = 1; q < 8; q++) m = fmaxf(m, sred[q]);
        const int e = (__float_as_int(m) >> 23) - 127;
        sbc = __int_as_float((127 - e) << 23);
        sei = e;
    }
    __syncthreads();
    const float sc = sbc;

    if (stage == 1) {
        if (c < 16) {
#pragma unroll
            for (int r = 0; r < 4; r++) {
                float4 wv = make_float4(out[r][0] * sc, out[r][1] * sc,
                                        out[r][2] * sc, out[r][3] * sc);
                *(float4*)(g_L4 + c * 4096 + (4 * rc + r) * NS + 4 * jc) = wv;
            }
#pragma unroll
            for (int cc = 0; cc < 4; cc++) {
                float4 wv = make_float4(out[0][cc] * sc, out[1][cc] * sc,
                                        out[2][cc] * sc, out[3][cc] * sc);
                *(float4*)(g_L4t + c * 4096 + (4 * jc + cc) * NS + 4 * rc) = wv;
            }
            if (tid == 0) g_e4[c] = eIn + sei;
        } else {
            const int v = c - 16;
#pragma unroll
            for (int r = 0; r < 4; r++) {
                float4 wv = make_float4(out[r][0] * sc, out[r][1] * sc,
                                        out[r][2] * sc, out[r][3] * sc);
                *(float4*)(g_L3 + v * 4096 + (4 * rc + r) * NS + 4 * jc) = wv;
            }
            if (tid == 0) g_e3[v] = eIn + sei;
        }
    } else {
        // NORMAL layout for wmma matrix_a (row-major)
#pragma unroll
        for (int r = 0; r < 4; r++) {
            float4 wv = make_float4(out[r][0] * sc, out[r][1] * sc,
                                    out[r][2] * sc, out[r][3] * sc);
            *(float4*)(g_L8n + c * 4096 + (4 * rc + r) * NS + 4 * jc) = wv;
        }
        if (tid == 0) g_e8[c] = eIn + sei;
    }
}

// ============================================================================
// final (grid 2048, 256 thr): P = L8[code>>3] @ L3[code&7] via WMMA bf16.
// C staged through smem (stride 68); normalize + permuted e4m3 encode.
// dyn smem: Abf 8KB | Bbf 8KB | Cs 64*68 fp32 (17408B)  => 33792 B
// ============================================================================
__global__ void __launch_bounds__(256) final_kernel() {
    extern __shared__ char dynFc[];
    __nv_bfloat16* Abf = (__nv_bfloat16*)dynFc;
    __nv_bfloat16* Bbf = (__nv_bfloat16*)(dynFc + 8192);
    float*         Cs  = (float*)(dynFc + 16384);   // stride 68

    __shared__ float sred[8];
    __shared__ float sbc;
    __shared__ int   sei;

    const int code = blockIdx.x;
    const int a = code >> 3;
    const int b = code & 7;
    const int tid  = threadIdx.x;
    const int lane = tid & 31;
    const int w    = tid >> 5;

    // stage A, B as bf16
    {
        const float4* Ag = (const float4*)(g_L8n + a * 4096);
        const float4* Bg = (const float4*)(g_L3  + b * 4096);
#pragma unroll
        for (int i = 0; i < 4; i++) {
            const int f = tid + 256 * i;
            const float4 va = Ag[f];
            const float4 vb = Bg[f];
            __nv_bfloat162* da = (__nv_bfloat162*)(Abf + 4 * f);
            da[0] = __floats2bfloat162_rn(va.x, va.y);
            da[1] = __floats2bfloat162_rn(va.z, va.w);
            __nv_bfloat162* db = (__nv_bfloat162*)(Bbf + 4 * f);
            db[0] = __floats2bfloat162_rn(vb.x, vb.y);
            db[1] = __floats2bfloat162_rn(vb.z, vb.w);
        }
    }
    __syncthreads();

    // wmma: warp w -> row-tile w>>1 (16 rows), col-tiles 2*(w&1), 2*(w&1)+1
    {
        const int rt = w >> 1;
        const int ct = (w & 1) * 2;
        wmma::fragment<wmma::accumulator, 16, 16, 16, float> acc0, acc1;
        wmma::fill_fragment(acc0, 0.0f);
        wmma::fill_fragment(acc1, 0.0f);
#pragma unroll
        for (int kt = 0; kt < 4; kt++) {
            wmma::fragment<wmma::matrix_a, 16, 16, 16, __nv_bfloat16, wmma::row_major> af;
            wmma::load_matrix_sync(af, Abf + rt * 16 * 64 + kt * 16, 64);
            wmma::fragment<wmma::matrix_b, 16, 16, 16, __nv_bfloat16, wmma::row_major> bf0, bf1;
            wmma::load_matrix_sync(bf0, Bbf + kt * 16 * 64 + ct * 16, 64);
            wmma::load_matrix_sync(bf1, Bbf + kt * 16 * 64 + (ct + 1) * 16, 64);
            wmma::mma_sync(acc0, af, bf0, acc0);
            wmma::mma_sync(acc1, af, bf1, acc1);
        }
        wmma::store_matrix_sync(Cs + rt * 16 * 68 + ct * 16,       acc0, 68, wmma::mem_row_major);
        wmma::store_matrix_sync(Cs + rt * 16 * 68 + (ct + 1) * 16, acc1, 68, wmma::mem_row_major);
    }
    __syncthreads();

    // epilogue: thread (jc, rc) owns rows k=4rc..4rc+3, cols o=4jc..4jc+3
    const int jc = tid & 15;
    const int rc = tid >> 4;
    float out[4][4];
    float mx = 0.f;
#pragma unroll
    for (int r = 0; r < 4; r++)
#pragma unroll
        for (int cc = 0; cc < 4; cc++) {
            const float v = Cs[(4 * rc + r) * 68 + 4 * jc + cc];
            out[r][cc] = v;
            mx = fmaxf(mx, v);
        }
#pragma unroll
    for (int off = 16; off > 0; off >>= 1)
        mx = fmaxf(mx, __shfl_xor_sync(0xffffffffu, mx, off));
    if (lane == 0) sred[w] = mx;
    __syncthreads();
    if (tid == 0) {
        float m = sred[0];
#pragma unroll
        for (int q = 1; q < 8; q++) m = fmaxf(m, sred[q]);
        const int e = (__float_as_int(m) >> 23) - 127;
        sbc = __int_as_float((127 - e) << 23);
        sei = e;
    }
    __syncthreads();
    const float sc = sbc;

    const int k0 = 4 * rc;
#pragma unroll
    for (int cc = 0; cc < 4; cc++) {
        const int o = 4 * jc + cc;
        const unsigned p01 = f2_e4m3x2(out[1][cc] * sc, out[0][cc] * sc);
        const unsigned p23 = f2_e4m3x2(out[3][cc] * sc, out[2][cc] * sc);
        unsigned* dst = (unsigned*)((char*)g_Pt4 + (size_t)code * 4096
                        + ((o < 32 ? 0 : 4) + (k0 >> 4)) * 512
                        + (o & 31) * 16 + (k0 & 15));
        *dst = p01 | (p23 << 16);
    }
    if (tid == 0) g_e11[code] = g_e8[a] + g_e3[b] + sei;
}

// ============================================================================
// main: one warp per element; inline ballot codes; fp8 table, half2 matvec
// (proven 162.1us version: depth-1 double buffer)
// ============================================================================
#define PREFETCH(MB, c)                                                       \
    {                                                                         \
        const uint4* __restrict__ tp = g_Pt4 + (size_t)(c) * 256 + lane;      \
        _Pragma("unroll")                                                     \
        for (int i = 0; i < 8; i++) MB[i] = tp[i * 32];                       \
    }

#define PROC8(u, av0, av1, acc)                                               \
    acc = __hfma2(e4m3x2_h2((unsigned short)(u).x),         as_h2((av0).x), acc); \
    acc = __hfma2(e4m3x2_h2((unsigned short)((u).x >> 16)), as_h2((av0).y), acc); \
    acc = __hfma2(e4m3x2_h2((unsigned short)(u).y),         as_h2((av0).z), acc); \
    acc = __hfma2(e4m3x2_h2((unsigned short)((u).y >> 16)), as_h2((av0).w), acc); \
    acc = __hfma2(e4m3x2_h2((unsigned short)(u).z),         as_h2((av1).x), acc); \
    acc = __hfma2(e4m3x2_h2((unsigned short)((u).z >> 16)), as_h2((av1).y), acc); \
    acc = __hfma2(e4m3x2_h2((unsigned short)(u).w),         as_h2((av1).z), acc); \
    acc = __hfma2(e4m3x2_h2((unsigned short)((u).w >> 16)), as_h2((av1).w), acc);

#define PACKSTORE(PP)                                                         \
    {                                                                         \
        const float ev = __shfl_sync(0xffffffffu, s_lo, 0);                   \
        int e = (__float_as_int(ev) >> 23) - 125;                             \
        e = max(-120, min(120, e));                                           \
        const float rsc = __int_as_float((127 - e) << 23);                    \
        s_lo *= rsc; s_hi *= rsc; ce += e;                                    \
        const float lo0 = __shfl_sync(0xffffffffu, s_lo, (2 * lane) & 31);    \
        const float lo1 = __shfl_sync(0xffffffffu, s_lo, (2 * lane + 1) & 31);\
        const float hi0 = __shfl_sync(0xffffffffu, s_hi, (2 * lane) & 31);    \
        const float hi1 = __shfl_sync(0xffffffffu, s_hi, (2 * lane + 1) & 31);\
        const float x0 = lane < 16 ? lo0 : hi0;                               \
        const float x1 = lane < 16 ? lo1 : hi1;                               \
        s_ah[wid][PP][lane] = __floats2half2_rn(x0, x1);                      \
        __syncwarp();                                                         \
    }

#define COMPUTE(MB, CODE)                                                     \
    {                                                                         \
        const uint4* __restrict__ ah = (const uint4*)s_ah[wid][p];            \
        uint4 au[8];                                                          \
        _Pragma("unroll")                                                     \
        for (int q = 0; q < 8; q++) au[q] = ah[q];                            \
        __half2 h0 = __float2half2_rn(0.f), h1 = h0, h2 = h0, h3 = h0;        \
        __half2 g0 = h0, g1 = h0, g2 = h0, g3 = h0;                           \
        PROC8(MB[0], au[0], au[1], h0)                                        \
        PROC8(MB[1], au[2], au[3], h1)                                        \
        PROC8(MB[2], au[4], au[5], h2)                                        \
        PROC8(MB[3], au[6], au[7], h3)                                        \
        PROC8(MB[4], au[0], au[1], g0)                                        \
        PROC8(MB[5], au[2], au[3], g1)                                        \
        PROC8(MB[6], au[4], au[5], g2)                                        \
        PROC8(MB[7], au[6], au[7], g3)                                        \
        const __half2 tc = __hadd2(__hadd2(h0, h1), __hadd2(h2, h3));         \
        const __half2 td = __hadd2(__hadd2(g0, g1), __hadd2(g2, g3));         \
        s_lo = __low2float(tc) + __high2float(tc);                            \
        s_hi = __low2float(td) + __high2float(td);                            \
        ce += g_e11[CODE];                                                    \
        p ^= 1;                                                               \
        PACKSTORE(p)                                                          \
    }

__device__ __forceinline__ int getcode(const unsigned* __restrict__ bw, int j) {
    const int base = 1 + LBLK * j;
    const unsigned lo = bw[base >> 5];
    const unsigned hi = bw[(base >> 5) + 1];
    return (int)(__brev(__funnelshift_r(lo, hi, base & 31)) >> 21);
}

__global__ void __launch_bounds__(128)
hmm_main_kernel(const int* __restrict__ y, float* __restrict__ outp) {
    __shared__ __align__(16) __half2 s_ah[4][2][32];
    __shared__ unsigned s_bw[4][34];

    const int tid  = threadIdx.x;
    const int lane = tid & 31;
    const int wid  = tid >> 5;
    const int b    = blockIdx.x * 4 + wid;
    const int* __restrict__ yrow = y + b * DIM;

#pragma unroll
    for (int ch = 0; ch < 32; ch++) {
        const unsigned w = __ballot_sync(0xffffffffu, yrow[ch * 32 + lane]);
        if (lane == 0) s_bw[wid][ch] = w;
    }
    if (lane == 0) { s_bw[wid][32] = 0u; s_bw[wid][33] = 0u; }
    __syncwarp();
    const unsigned* __restrict__ bw = s_bw[wid];

    const int y0 = (int)(bw[0] & 1u);
    float s_lo = g_Pi[lane]      * (y0 ? g_E1[lane]      : g_E0[lane]);
    float s_hi = g_Pi[lane + 32] * (y0 ? g_E1[lane + 32] : g_E0[lane + 32]);

    int ce = 0, p = 0;
    PACKSTORE(0)

    uint4 mA[8], mB[8];
    int cA = getcode(bw, 0), cB;
    PREFETCH(mA, cA)

    for (int jj = 0; jj < 92; jj += 2) {
        cB = getcode(bw, jj + 1);
        PREFETCH(mB, cB)
        COMPUTE(mA, cA)
        cA = getcode(bw, jj + 2);
        PREFETCH(mA, cA)
        COMPUTE(mB, cB)
    }
    COMPUTE(mA, cA)   // j = 92 (prefetched at jj = 90)

    float v = s_lo + s_hi;
#pragma unroll
    for (int off = 16; off > 0; off >>= 1)
        v += __shfl_xor_sync(0xffffffffu, v, off);

    if (lane == 0) {
        const double logp = (double)logf(v) + (double)ce * 0.6931471805599453;
        atomicAdd(&g_acc, logp);
        __threadfence();
        const unsigned done = atomicAdd(&g_done, 1u);
        if (done == (unsigned)(BATCH - 1)) {
            outp[0] = (float)(g_acc * (1.0 / 4096.0));
        }
    }
}

extern "C" void kernel_launch(void* const* d_in, const int* in_sizes, int n_in,
                              void* d_out, int out_size) {
    const int*   y  = (const int*)  d_in[0];
    const float* Tr = (const float*)d_in[1];
    const float* Em = (const float*)d_in[2];
    const float* Pi = (const float*)d_in[3];

    cudaFuncSetAttribute(prep_kernel,
        cudaFuncAttributeMaxDynamicSharedMemorySize, 67584);
    cudaFuncSetAttribute(combine_kernel,
        cudaFuncAttributeMaxDynamicSharedMemorySize, 49152);
    cudaFuncSetAttribute(final_kernel,
        cudaFuncAttributeMaxDynamicSharedMemorySize, 33792);

    prep_kernel<<<1, 1024, 67584>>>(Tr, Em, Pi);
    combine_kernel<<<24, 256, 49152>>>(1);    // L4 (+L4t) and L3
    combine_kernel<<<256, 256, 49152>>>(2);   // L8n (normal, for wmma)
    final_kernel<<<2048, 256, 33792>>>();     // WMMA bf16 -> fp8 table + e11
    hmm_main_kernel<<<BATCH / 4, 128>>>(y, (float*)d_out);
}

// round 17
// speedup vs baseline: 1.2068x; 1.0010x over previous
#include <cuda_runtime.h>
#include <cuda_bf16.h>
#include <cuda_fp16.h>
#include <mma.h>

#define BATCH 4096
#define DIM   1024
#define NS    64
#define LBLK  11
#define NCODE 2048

typedef unsigned long long u64;
using namespace nvcuda;

// ---- device-global scratch (static; no runtime alloc) ----
__device__ float  g_E0[NS], g_E1[NS], g_Pi[NS];
__device__ float  g_L1[2 * NS * NS];                  // normal [k][o]
__device__ float  g_L2[4 * NS * NS],  g_L2t[4 * NS * NS];
__device__ float  g_L4[16 * NS * NS], g_L4t[16 * NS * NS];
__device__ __nv_bfloat16 g_L3b[8 * NS * NS];          // bf16 (wmma B)
__device__ __nv_bfloat16 g_L8b[256 * NS * NS];        // bf16 (wmma A)
__device__ int    g_e1[2], g_e2[4], g_e3[8], g_e4[16], g_e8[256], g_e11[NCODE];
// fp8 e4m3 table, permuted: byte(c,o,k) = c*4096 + ((o<32?0:4)+(k>>4))*512 + (o&31)*16 + (k&15)
__device__ uint4  g_Pt4[NCODE * 256];    // 8 MB
__device__ double g_acc;
__device__ unsigned g_done;

// ---- packed helpers ----
__device__ __forceinline__ u64 pk2(float lo, float hi) {
    u64 r; asm("mov.b64 %0, {%1,%2};" : "=l"(r) : "f"(lo), "f"(hi)); return r;
}
__device__ __forceinline__ void upk2(u64 v, float &lo, float &hi) {
    asm("mov.b64 {%0,%1}, %2;" : "=f"(lo), "=f"(hi) : "l"(v));
}
__device__ __forceinline__ u64 fma2(u64 a, u64 b, u64 c) {
    u64 d; asm("fma.rn.f32x2 %0, %1, %2, %3;" : "=l"(d) : "l"(a), "l"(b), "l"(c)); return d;
}
__device__ __forceinline__ unsigned short f2_e4m3x2(float hi, float lo) {
    unsigned short r;
    asm("cvt.rn.satfinite.e4m3x2.f32 %0, %1, %2;" : "=h"(r) : "f"(hi), "f"(lo));
    return r;
}
__device__ __forceinline__ __half2 e4m3x2_h2(unsigned short s) {
    unsigned r;
    asm("cvt.rn.f16x2.e4m3x2 %0, %1;" : "=r"(r) : "h"(s));
    return *(__half2*)&r;
}
__device__ __forceinline__ __half2 as_h2(unsigned w) { return *(__half2*)&w; }
__device__ __forceinline__ unsigned bf2u(__nv_bfloat162 v) { return *(unsigned*)&v; }

// ---- classic 4x4 GEMM (prep L2 stage only) ----
__device__ __forceinline__ void gemm4x4(const float* __restrict__ At, int strideF,
                                        const float* __restrict__ B,
                                        int jc, int rc, float out[4][4]) {
    u64 acc[4][2];
#pragma unroll
    for (int r = 0; r < 4; r++) { acc[r][0] = 0ull; acc[r][1] = 0ull; }
#pragma unroll 16
    for (int k = 0; k < NS; k++) {
        const float4 av = *(const float4*)(At + k * strideF + 4 * rc);
        const float4 bv = *(const float4*)(B  + k * NS      + 4 * jc);
        const u64 c01 = ((const u64*)&bv)[0];
        const u64 c23 = ((const u64*)&bv)[1];
        const u64 a0 = pk2(av.x, av.x), a1 = pk2(av.y, av.y);
        const u64 a2 = pk2(av.z, av.z), a3 = pk2(av.w, av.w);
        acc[0][0] = fma2(c01, a0, acc[0][0]); acc[0][1] = fma2(c23, a0, acc[0][1]);
        acc[1][0] = fma2(c01, a1, acc[1][0]); acc[1][1] = fma2(c23, a1, acc[1][1]);
        acc[2][0] = fma2(c01, a2, acc[2][0]); acc[2][1] = fma2(c23, a2, acc[2][1]);
        acc[3][0] = fma2(c01, a3, acc[3][0]); acc[3][1] = fma2(c23, a3, acc[3][1]);
    }
#pragma unroll
    for (int r = 0; r < 4; r++) {
        upk2(acc[r][0], out[r][0], out[r][1]);
        upk2(acc[r][1], out[r][2], out[r][3]);
    }
}

// ---- duplicated-A 4x4 GEMM: Atd[k*128 + 2r] = Atd[k*128 + 2r+1] = A[r][k] ----
__device__ __forceinline__ void gemm4x4_dup(const float* __restrict__ Atd,
                                            const float* __restrict__ B,
                                            int jc, int rc, float out[4][4]) {
    u64 acc[4][2];
#pragma unroll
    for (int r = 0; r < 4; r++) { acc[r][0] = 0ull; acc[r][1] = 0ull; }
#pragma unroll 16
    for (int k = 0; k < NS; k++) {
        const ulonglong2 a01 = *(const ulonglong2*)(Atd + k * 128 + 8 * rc);
        const ulonglong2 a23 = *(const ulonglong2*)(Atd + k * 128 + 8 * rc + 4);
        const float4 bv = *(const float4*)(B + k * NS + 4 * jc);
        const u64 c01 = ((const u64*)&bv)[0];
        const u64 c23 = ((const u64*)&bv)[1];
        acc[0][0] = fma2(c01, a01.x, acc[0][0]); acc[0][1] = fma2(c23, a01.x, acc[0][1]);
        acc[1][0] = fma2(c01, a01.y, acc[1][0]); acc[1][1] = fma2(c23, a01.y, acc[1][1]);
        acc[2][0] = fma2(c01, a23.x, acc[2][0]); acc[2][1] = fma2(c23, a23.x, acc[2][1]);
        acc[3][0] = fma2(c01, a23.y, acc[3][0]); acc[3][1] = fma2(c23, a23.y, acc[3][1]);
    }
#pragma unroll
    for (int r = 0; r < 4; r++) {
        upk2(acc[r][0], out[r][0], out[r][1]);
        upk2(acc[r][1], out[r][2], out[r][3]);
    }
}

__device__ __forceinline__ void stage_dup(const float* __restrict__ src_t,
                                          float* __restrict__ dst) {
    const int tid = threadIdx.x;
#pragma unroll
    for (int i = 0; i < 4; i++) {
        const int f  = tid + 256 * i;
        const float4 v = ((const float4*)src_t)[f];
        const int k  = f >> 4, r4 = (f & 15) * 4;
        float4* d = (float4*)(dst + k * 128 + 2 * r4);
        d[0] = make_float4(v.x, v.x, v.y, v.y);
        d[1] = make_float4(v.z, v.z, v.w, v.w);
    }
}
__device__ __forceinline__ void stage_nrm(const float* __restrict__ src,
                                          float* __restrict__ dst) {
    const int tid = threadIdx.x;
#pragma unroll
    for (int i = 0; i < 4; i++)
        ((float4*)dst)[tid + 256 * i] = ((const float4*)src)[tid + 256 * i];
}

// ============================================================================
// prep: softmaxes + L1 + L2 in ONE kernel (unchanged)
// ============================================================================
__global__ void __launch_bounds__(1024)
prep_kernel(const float* __restrict__ Tr,
            const float* __restrict__ Em,
            const float* __restrict__ Pi) {
    extern __shared__ float dynP[];
    float* sL1n = dynP;
    float* sL1t = dynP + 8192;

    __shared__ float rowm[NS], rowinv[NS];
    __shared__ float sE[2][NS];
    __shared__ float sred[32];
    __shared__ float sbcA[4];
    __shared__ int   seiA[4];

    const int tid  = threadIdx.x;
    const int lane = tid & 31;
    const int w    = tid >> 5;

    if (tid == 0) { g_acc = 0.0; g_done = 0u; }

#pragma unroll
    for (int rr = 0; rr < 2; rr++) {
        const int r = w + rr * 32;
        const float v0 = Tr[r * NS + lane];
        const float v1 = Tr[r * NS + lane + 32];
        float m = fmaxf(v0, v1);
#pragma unroll
        for (int off = 16; off > 0; off >>= 1)
            m = fmaxf(m, __shfl_xor_sync(0xffffffffu, m, off));
        const float e0 = expf(v0 - m), e1v = expf(v1 - m);
        float s = e0 + e1v;
#pragma unroll
        for (int off = 16; off > 0; off >>= 1)
            s += __shfl_xor_sync(0xffffffffu, s, off);
        if (lane == 0) { rowm[r] = m; rowinv[r] = 1.f / s; }
    }
    if (tid < NS) {
        const float a = Em[tid * 2 + 0], b2 = Em[tid * 2 + 1];
        const float mm = fmaxf(a, b2);
        const float ea = expf(a - mm), eb = expf(b2 - mm);
        const float is = 1.f / (ea + eb);
        sE[0][tid] = ea * is;  sE[1][tid] = eb * is;
        g_E0[tid] = ea * is;   g_E1[tid] = eb * is;
    }
    if (w == 1) {
        const float v0 = Pi[lane], v1 = Pi[lane + 32];
        float m = fmaxf(v0, v1);
#pragma unroll
        for (int off = 16; off > 0; off >>= 1)
            m = fmaxf(m, __shfl_xor_sync(0xffffffffu, m, off));
        const float e0 = expf(v0 - m), e1v = expf(v1 - m);
        float s = e0 + e1v;
#pragma unroll
        for (int off = 16; off > 0; off >>= 1)
            s += __shfl_xor_sync(0xffffffffu, s, off);
        const float inv = 1.f / s;
        g_Pi[lane] = e0 * inv;  g_Pi[lane + 32] = e1v * inv;
    }
    __syncthreads();

    for (int y = 0; y < 2; y++) {
        float vv[4], vmax = 0.f;
#pragma unroll
        for (int i = 0; i < 4; i++) {
            const int idx = tid + i * 1024;
            const int k = idx >> 6, o = idx & 63;
            const float v = expf(Tr[idx] - rowm[k]) * rowinv[k] * sE[y][o];
            vv[i] = v; vmax = fmaxf(vmax, v);
        }
#pragma unroll
        for (int off = 16; off > 0; off >>= 1)
            vmax = fmaxf(vmax, __shfl_xor_sync(0xffffffffu, vmax, off));
        if (lane == 0) sred[w] = vmax;
        __syncthreads();
        if (tid < 32) {
            float m = sred[lane];
#pragma unroll
            for (int off = 16; off > 0; off >>= 1)
                m = fmaxf(m, __shfl_xor_sync(0xffffffffu, m, off));
            if (lane == 0) {
                const int e = (__float_as_int(m) >> 23) - 127;
                seiA[y] = e;  g_e1[y] = e;
                sbcA[y] = __int_as_float((127 - e) << 23);
            }
        }
        __syncthreads();
        const float sc = sbcA[y];
#pragma unroll
        for (int i = 0; i < 4; i++) {
            const int idx = tid + i * 1024;
            const int k = idx >> 6, o = idx & 63;
            const float v = vv[i] * sc;
            sL1n[y * 4096 + idx]         = v;
            sL1t[y * 4352 + o * 68 + k]  = v;
            g_L1[y * 4096 + idx]         = v;
        }
        __syncthreads();
    }

    {
        const int g    = tid >> 8;
        const int gtid = tid & 255;
        const int jc   = gtid & 15;
        const int rc   = gtid >> 4;
        float out[4][4];
        gemm4x4(sL1t + (g >> 1) * 4352, 68, sL1n + (g & 1) * 4096, jc, rc, out);
        float mx = 0.f;
#pragma unroll
        for (int r = 0; r < 4; r++)
#pragma unroll
            for (int c = 0; c < 4; c++) mx = fmaxf(mx, out[r][c]);
#pragma unroll
        for (int off = 16; off > 0; off >>= 1)
            mx = fmaxf(mx, __shfl_xor_sync(0xffffffffu, mx, off));
        if (lane == 0) sred[w] = mx;
        __syncthreads();
        if (tid < 4) {
            float m = sred[8 * tid];
#pragma unroll
            for (int q = 1; q < 8; q++) m = fmaxf(m, sred[8 * tid + q]);
            const int e = (__float_as_int(m) >> 23) - 127;
            sbcA[tid] = __int_as_float((127 - e) << 23);
            g_e2[tid] = seiA[tid >> 1] + seiA[tid & 1] + e;
        }
        __syncthreads();
        const float sc = sbcA[g];
#pragma unroll
        for (int r = 0; r < 4; r++) {
            float4 wv = make_float4(out[r][0] * sc, out[r][1] * sc,
                                    out[r][2] * sc, out[r][3] * sc);
            *(float4*)(g_L2 + g * 4096 + (4 * rc + r) * NS + 4 * jc) = wv;
        }
#pragma unroll
        for (int c = 0; c < 4; c++) {
            float4 wv = make_float4(out[0][c] * sc, out[1][c] * sc,
                                    out[2][c] * sc, out[3][c] * sc);
            *(float4*)(g_L2t + g * 4096 + (4 * jc + c) * NS + 4 * rc) = wv;
        }
    }
}

// ============================================================================
// combine: stage1 grid 24 (L4+L4t fp32, L3 bf16), stage2 grid 256 (L8 bf16)
// ============================================================================
__global__ void __launch_bounds__(256) combine_kernel(int stage) {
    extern __shared__ float dynC[];
    float* Atd = dynC;
    float* Bn  = dynC + 8192;

    __shared__ float sred[8];
    __shared__ float sbc;
    __shared__ int   sei;

    const int c = blockIdx.x;
    const int tid  = threadIdx.x;
    const int lane = tid & 31;
    const int w    = tid >> 5;
    const int jc   = tid & 15;
    const int rc   = tid >> 4;

    const float *Asrc_t, *Bsrc; int eIn;
    if (stage == 1) {
        if (c < 16) { Asrc_t = g_L2t + (c >> 2) * 4096; Bsrc = g_L2 + (c & 3) * 4096;
                      eIn = g_e2[c >> 2] + g_e2[c & 3]; }
        else        { const int v = c - 16;
                      Asrc_t = g_L2t + (v >> 1) * 4096; Bsrc = g_L1 + (v & 1) * 4096;
                      eIn = g_e2[v >> 1] + g_e1[v & 1]; }
    } else {
        Asrc_t = g_L4t + (c >> 4) * 4096; Bsrc = g_L4 + (c & 15) * 4096;
        eIn = g_e4[c >> 4] + g_e4[c & 15];
    }

    stage_dup(Asrc_t, Atd);
    stage_nrm(Bsrc, Bn);
    __syncthreads();

    float out[4][4];
    gemm4x4_dup(Atd, Bn, jc, rc, out);
    float mx = 0.f;
#pragma unroll
    for (int r = 0; r < 4; r++)
#pragma unroll
        for (int cc = 0; cc < 4; cc++) mx = fmaxf(mx, out[r][cc]);
#pragma unroll
    for (int off = 16; off > 0; off >>= 1)
        mx = fmaxf(mx, __shfl_xor_sync(0xffffffffu, mx, off));
    if (lane == 0) sred[w] = mx;
    __syncthreads();
    if (tid == 0) {
        float m = sred[0];
#pragma unroll
        for (int q = 1; q < 8; q++) m = fmaxf(m, sred[q]);
        const int e = (__float_as_int(m) >> 23) - 127;
        sbc = __int_as_float((127 - e) << 23);
        sei = e;
    }
    __syncthreads();
    const float sc = sbc;

    if (stage == 1) {
        if (c < 16) {
#pragma unroll
            for (int r = 0; r < 4; r++) {
                float4 wv = make_float4(out[r][0] * sc, out[r][1] * sc,
                                        out[r][2] * sc, out[r][3] * sc);
                *(float4*)(g_L4 + c * 4096 + (4 * rc + r) * NS + 4 * jc) = wv;
            }
#pragma unroll
            for (int cc = 0; cc < 4; cc++) {
                float4 wv = make_float4(out[0][cc] * sc, out[1][cc] * sc,
                                        out[2][cc] * sc, out[3][cc] * sc);
                *(float4*)(g_L4t + c * 4096 + (4 * jc + cc) * NS + 4 * rc) = wv;
            }
            if (tid == 0) g_e4[c] = eIn + sei;
        } else {
            const int v = c - 16;
#pragma unroll
            for (int r = 0; r < 4; r++) {
                const unsigned u0 = bf2u(__floats2bfloat162_rn(out[r][0] * sc, out[r][1] * sc));
                const unsigned u1 = bf2u(__floats2bfloat162_rn(out[r][2] * sc, out[r][3] * sc));
                *(uint2*)(g_L3b + v * 4096 + (4 * rc + r) * NS + 4 * jc) = make_uint2(u0, u1);
            }
            if (tid == 0) g_e3[v] = eIn + sei;
        }
    } else {
        // bf16 normal layout for wmma matrix_a (row-major)
#pragma unroll
        for (int r = 0; r < 4; r++) {
            const unsigned u0 = bf2u(__floats2bfloat162_rn(out[r][0] * sc, out[r][1] * sc));
            const unsigned u1 = bf2u(__floats2bfloat162_rn(out[r][2] * sc, out[r][3] * sc));
            *(uint2*)(g_L8b + c * 4096 + (4 * rc + r) * NS + 4 * jc) = make_uint2(u0, u1);
        }
        if (tid == 0) g_e8[c] = eIn + sei;
    }
}

// ============================================================================
// final (grid 2048, 256 thr): P = L8b[code>>3] @ L3b[code&7] via WMMA bf16.
// bf16 operands from global, fragment-level max, float4 epilogue.
// dyn smem: Abf 8KB | Bbf 8KB | Cs 64*68 fp32 (17408B)  => 33792 B
// ============================================================================
__global__ void __launch_bounds__(256) final_kernel() {
    extern __shared__ char dynFc[];
    __nv_bfloat16* Abf = (__nv_bfloat16*)dynFc;
    __nv_bfloat16* Bbf = (__nv_bfloat16*)(dynFc + 8192);
    float*         Cs  = (float*)(dynFc + 16384);   // stride 68

    __shared__ float sred[8];
    __shared__ float sbc;
    __shared__ int   sei;

    const int code = blockIdx.x;
    const int a = code >> 3;
    const int b = code & 7;
    const int tid  = threadIdx.x;
    const int lane = tid & 31;
    const int w    = tid >> 5;

    // stage bf16 operands directly (no conversion)
    {
        const uint4* Ag = (const uint4*)(g_L8b + a * 4096);
        const uint4* Bg = (const uint4*)(g_L3b + b * 4096);
        uint4* As = (uint4*)Abf;
        uint4* Bs = (uint4*)Bbf;
#pragma unroll
        for (int i = 0; i < 2; i++) {
            As[tid + 256 * i] = Ag[tid + 256 * i];
            Bs[tid + 256 * i] = Bg[tid + 256 * i];
        }
    }
    __syncthreads();

    // wmma: warp w -> row-tile w>>1 (16 rows), col-tiles 2*(w&1), 2*(w&1)+1
    float wmx = 0.f;
    {
        const int rt = w >> 1;
        const int ct = (w & 1) * 2;
        wmma::fragment<wmma::accumulator, 16, 16, 16, float> acc0, acc1;
        wmma::fill_fragment(acc0, 0.0f);
        wmma::fill_fragment(acc1, 0.0f);
#pragma unroll
        for (int kt = 0; kt < 4; kt++) {
            wmma::fragment<wmma::matrix_a, 16, 16, 16, __nv_bfloat16, wmma::row_major> af;
            wmma::load_matrix_sync(af, Abf + rt * 16 * 64 + kt * 16, 64);
            wmma::fragment<wmma::matrix_b, 16, 16, 16, __nv_bfloat16, wmma::row_major> bf0, bf1;
            wmma::load_matrix_sync(bf0, Bbf + kt * 16 * 64 + ct * 16, 64);
            wmma::load_matrix_sync(bf1, Bbf + kt * 16 * 64 + (ct + 1) * 16, 64);
            wmma::mma_sync(acc0, af, bf0, acc0);
            wmma::mma_sync(acc1, af, bf1, acc1);
        }
        // fragment-level max (warp tiles cover the whole matrix across the block)
#pragma unroll
        for (int i = 0; i < acc0.num_elements; i++) {
            wmx = fmaxf(wmx, acc0.x[i]);
            wmx = fmaxf(wmx, acc1.x[i]);
        }
        wmma::store_matrix_sync(Cs + rt * 16 * 68 + ct * 16,       acc0, 68, wmma::mem_row_major);
        wmma::store_matrix_sync(Cs + rt * 16 * 68 + (ct + 1) * 16, acc1, 68, wmma::mem_row_major);
    }
#pragma unroll
    for (int off = 16; off > 0; off >>= 1)
        wmx = fmaxf(wmx, __shfl_xor_sync(0xffffffffu, wmx, off));
    if (lane == 0) sred[w] = wmx;
    __syncthreads();
    if (tid == 0) {
        float m = sred[0];
#pragma unroll
        for (int q = 1; q < 8; q++) m = fmaxf(m, sred[q]);
        const int e = (__float_as_int(m) >> 23) - 127;
        sbc = __int_as_float((127 - e) << 23);
        sei = e;
    }
    __syncthreads();
    const float sc = sbc;

    // epilogue: thread (jc, rc) owns rows k=4rc..4rc+3, cols o=4jc..4jc+3
    const int jc = tid & 15;
    const int rc = tid >> 4;
    float out[4][4];
#pragma unroll
    for (int r = 0; r < 4; r++) {
        const float4 v = *(const float4*)(Cs + (4 * rc + r) * 68 + 4 * jc);
        out[r][0] = v.x; out[r][1] = v.y; out[r][2] = v.z; out[r][3] = v.w;
    }

    const int k0 = 4 * rc;
#pragma unroll
    for (int cc = 0; cc < 4; cc++) {
        const int o = 4 * jc + cc;
        const unsigned p01 = f2_e4m3x2(out[1][cc] * sc, out[0][cc] * sc);
        const unsigned p23 = f2_e4m3x2(out[3][cc] * sc, out[2][cc] * sc);
        unsigned* dst = (unsigned*)((char*)g_Pt4 + (size_t)code * 4096
                        + ((o < 32 ? 0 : 4) + (k0 >> 4)) * 512
                        + (o & 31) * 16 + (k0 & 15));
        *dst = p01 | (p23 << 16);
    }
    if (tid == 0) g_e11[code] = g_e8[a] + g_e3[b] + sei;
}

// ============================================================================
// main: one warp per element; inline ballot codes; fp8 table, half2 matvec
// (proven version: depth-1 double buffer)
// ============================================================================
#define PREFETCH(MB, c)                                                       \
    {                                                                         \
        const uint4* __restrict__ tp = g_Pt4 + (size_t)(c) * 256 + lane;      \
        _Pragma("unroll")                                                     \
        for (int i = 0; i < 8; i++) MB[i] = tp[i * 32];                       \
    }

#define PROC8(u, av0, av1, acc)                                               \
    acc = __hfma2(e4m3x2_h2((unsigned short)(u).x),         as_h2((av0).x), acc); \
    acc = __hfma2(e4m3x2_h2((unsigned short)((u).x >> 16)), as_h2((av0).y), acc); \
    acc = __hfma2(e4m3x2_h2((unsigned short)(u).y),         as_h2((av0).z), acc); \
    acc = __hfma2(e4m3x2_h2((unsigned short)((u).y >> 16)), as_h2((av0).w), acc); \
    acc = __hfma2(e4m3x2_h2((unsigned short)(u).z),         as_h2((av1).x), acc); \
    acc = __hfma2(e4m3x2_h2((unsigned short)((u).z >> 16)), as_h2((av1).y), acc); \
    acc = __hfma2(e4m3x2_h2((unsigned short)(u).w),         as_h2((av1).z), acc); \
    acc = __hfma2(e4m3x2_h2((unsigned short)((u).w >> 16)), as_h2((av1).w), acc);

#define PACKSTORE(PP)                                                         \
    {                                                                         \
        const float ev = __shfl_sync(0xffffffffu, s_lo, 0);                   \
        int e = (__float_as_int(ev) >> 23) - 125;                             \
        e = max(-120, min(120, e));                                           \
        const float rsc = __int_as_float((127 - e) << 23);                    \
        s_lo *= rsc; s_hi *= rsc; ce += e;                                    \
        const float lo0 = __shfl_sync(0xffffffffu, s_lo, (2 * lane) & 31);    \
        const float lo1 = __shfl_sync(0xffffffffu, s_lo, (2 * lane + 1) & 31);\
        const float hi0 = __shfl_sync(0xffffffffu, s_hi, (2 * lane) & 31);    \
        const float hi1 = __shfl_sync(0xffffffffu, s_hi, (2 * lane + 1) & 31);\
        const float x0 = lane < 16 ? lo0 : hi0;                               \
        const float x1 = lane < 16 ? lo1 : hi1;                               \
        s_ah[wid][PP][lane] = __floats2half2_rn(x0, x1);                      \
        __syncwarp();                                                         \
    }

#define COMPUTE(MB, CODE)                                                     \
    {                                                                         \
        const uint4* __restrict__ ah = (const uint4*)s_ah[wid][p];            \
        uint4 au[8];                                                          \
        _Pragma("unroll")                                                     \
        for (int q = 0; q < 8; q++) au[q] = ah[q];                            \
        __half2 h0 = __float2half2_rn(0.f), h1 = h0, h2 = h0, h3 = h0;        \
        __half2 g0 = h0, g1 = h0, g2 = h0, g3 = h0;                           \
        PROC8(MB[0], au[0], au[1], h0)                                        \
        PROC8(MB[1], au[2], au[3], h1)                                        \
        PROC8(MB[2], au[4], au[5], h2)                                        \
        PROC8(MB[3], au[6], au[7], h3)                                        \
        PROC8(MB[4], au[0], au[1], g0)                                        \
        PROC8(MB[5], au[2], au[3], g1)                                        \
        PROC8(MB[6], au[4], au[5], g2)                                        \
        PROC8(MB[7], au[6], au[7], g3)                                        \
        const __half2 tc = __hadd2(__hadd2(h0, h1), __hadd2(h2, h3));         \
        const __half2 td = __hadd2(__hadd2(g0, g1), __hadd2(g2, g3));         \
        s_lo = __low2float(tc) + __high2float(tc);                            \
        s_hi = __low2float(td) + __high2float(td);                            \
        ce += g_e11[CODE];                                                    \
        p ^= 1;                                                               \
        PACKSTORE(p)                                                          \
    }

__device__ __forceinline__ int getcode(const unsigned* __restrict__ bw, int j) {
    const int base = 1 + LBLK * j;
    const unsigned lo = bw[base >> 5];
    const unsigned hi = bw[(base >> 5) + 1];
    return (int)(__brev(__funnelshift_r(lo, hi, base & 31)) >> 21);
}

__global__ void __launch_bounds__(128)
hmm_main_kernel(const int* __restrict__ y, float* __restrict__ outp) {
    __shared__ __align__(16) __half2 s_ah[4][2][32];
    __shared__ unsigned s_bw[4][34];

    const int tid  = threadIdx.x;
    const int lane = tid & 31;
    const int wid  = tid >> 5;
    const int b    = blockIdx.x * 4 + wid;
    const int* __restrict__ yrow = y + b * DIM;

#pragma unroll
    for (int ch = 0; ch < 32; ch++) {
        const unsigned w = __ballot_sync(0xffffffffu, yrow[ch * 32 + lane]);
        if (lane == 0) s_bw[wid][ch] = w;
    }
    if (lane == 0) { s_bw[wid][32] = 0u; s_bw[wid][33] = 0u; }
    __syncwarp();
    const unsigned* __restrict__ bw = s_bw[wid];

    const int y0 = (int)(bw[0] & 1u);
    float s_lo = g_Pi[lane]      * (y0 ? g_E1[lane]      : g_E0[lane]);
    float s_hi = g_Pi[lane + 32] * (y0 ? g_E1[lane + 32] : g_E0[lane + 32]);

    int ce = 0, p = 0;
    PACKSTORE(0)

    uint4 mA[8], mB[8];
    int cA = getcode(bw, 0), cB;
    PREFETCH(mA, cA)

    for (int jj = 0; jj < 92; jj += 2) {
        cB = getcode(bw, jj + 1);
        PREFETCH(mB, cB)
        COMPUTE(mA, cA)
        cA = getcode(bw, jj + 2);
        PREFETCH(mA, cA)
        COMPUTE(mB, cB)
    }
    COMPUTE(mA, cA)   // j = 92 (prefetched at jj = 90)

    float v = s_lo + s_hi;
#pragma unroll
    for (int off = 16; off > 0; off >>= 1)
        v += __shfl_xor_sync(0xffffffffu, v, off);

    if (lane == 0) {
        const double logp = (double)logf(v) + (double)ce * 0.6931471805599453;
        atomicAdd(&g_acc, logp);
        __threadfence();
        const unsigned done = atomicAdd(&g_done, 1u);
        if (done == (unsigned)(BATCH - 1)) {
            outp[0] = (float)(g_acc * (1.0 / 4096.0));
        }
    }
}

extern "C" void kernel_launch(void* const* d_in, const int* in_sizes, int n_in,
                              void* d_out, int out_size) {
    const int*   y  = (const int*)  d_in[0];
    const float* Tr = (const float*)d_in[1];
    const float* Em = (const float*)d_in[2];
    const float* Pi = (const float*)d_in[3];

    cudaFuncSetAttribute(prep_kernel,
        cudaFuncAttributeMaxDynamicSharedMemorySize, 67584);
    cudaFuncSetAttribute(combine_kernel,
        cudaFuncAttributeMaxDynamicSharedMemorySize, 49152);
    cudaFuncSetAttribute(final_kernel,
        cudaFuncAttributeMaxDynamicSharedMemorySize, 33792);

    prep_kernel<<<1, 1024, 67584>>>(Tr, Em, Pi);
    combine_kernel<<<24, 256, 49152>>>(1);    // L4 (+L4t) and L3b (bf16)
    combine_kernel<<<256, 256, 49152>>>(2);   // L8b (bf16, for wmma)
    final_kernel<<<2048, 256, 33792>>>();     // WMMA bf16 -> fp8 table + e11
    hmm_main_kernel<<<BATCH / 4, 128>>>(y, (float*)d_out);
}